// round 1
// baseline (speedup 1.0000x reference)
#include <cuda_runtime.h>

#define HEADS 8
#define DIM_HEAD 64
#define BATCH 4
#define SEQ 2048
#define DMODEL 512
#define M_ROWS (BATCH * SEQ)           // 8192
#define QK_SCALE 0.125f                // 64^-0.5

// Scratch (device-global; no allocation allowed)
__device__ float g_q[BATCH * HEADS * SEQ * DIM_HEAD];   // [b,h,n,d], pre-scaled
__device__ float g_k[BATCH * HEADS * SEQ * DIM_HEAD];
__device__ float g_v[BATCH * HEADS * SEQ * DIM_HEAD];
__device__ float g_o[BATCH * SEQ * DMODEL];             // [b,n,h*64+d]

// ---------------------------------------------------------------------------
// Tiled fp32 GEMM: C[M=8192, 512] = A[8192, 512] @ W[512, 512]
// MODE 0/1/2: A = external (query), C = g_q/g_k/g_v in split-head layout
//             (MODE 0 additionally scales by QK_SCALE)
// MODE 3:     A = g_o, C = external output, row-major
// ---------------------------------------------------------------------------
template <int MODE>
__global__ __launch_bounds__(256)
void gemm_kernel(const float* __restrict__ Aext,
                 const float* __restrict__ W,
                 float* __restrict__ Cext)
{
    __shared__ float As[16][64];   // [k][m]
    __shared__ float Bs[16][64];   // [k][c]

    const float* __restrict__ A = (MODE == 3) ? g_o : Aext;

    const int tid = threadIdx.x;
    const int m0 = blockIdx.y * 64;
    const int c0 = blockIdx.x * 64;
    const int tx = tid & 15;       // col group
    const int ty = tid >> 4;       // row group

    const int arow = tid >> 2;     // 0..63
    const int aq   = tid & 3;      // float4 index within 16-col strip
    const int brow = tid >> 4;     // 0..15
    const int bq   = tid & 15;     // float4 col

    float acc[4][4] = {};

    for (int k0 = 0; k0 < DMODEL; k0 += 16) {
        __syncthreads();
        float4 a = *(const float4*)(A + (size_t)(m0 + arow) * DMODEL + k0 + aq * 4);
        As[aq * 4 + 0][arow] = a.x;
        As[aq * 4 + 1][arow] = a.y;
        As[aq * 4 + 2][arow] = a.z;
        As[aq * 4 + 3][arow] = a.w;
        *(float4*)(&Bs[brow][bq * 4]) =
            *(const float4*)(W + (size_t)(k0 + brow) * DMODEL + c0 + bq * 4);
        __syncthreads();

#pragma unroll
        for (int k = 0; k < 16; k++) {
            float4 ra = *(const float4*)(&As[k][ty * 4]);
            float4 rb = *(const float4*)(&Bs[k][tx * 4]);
            float pa[4] = {ra.x, ra.y, ra.z, ra.w};
            float pb[4] = {rb.x, rb.y, rb.z, rb.w};
#pragma unroll
            for (int i = 0; i < 4; i++)
#pragma unroll
                for (int j = 0; j < 4; j++)
                    acc[i][j] += pa[i] * pb[j];
        }
    }

#pragma unroll
    for (int i = 0; i < 4; i++) {
        const int m = m0 + ty * 4 + i;
        const int b = m >> 11;          // m / 2048
        const int n = m & 2047;
#pragma unroll
        for (int j = 0; j < 4; j++) {
            const int c = c0 + tx * 4 + j;
            float v = acc[i][j];
            if (MODE == 0) v *= QK_SCALE;
            if (MODE < 3) {
                const int h = c >> 6;
                const int d = c & 63;
                float* dst = (MODE == 0) ? g_q : (MODE == 1) ? g_k : g_v;
                dst[((((size_t)b * HEADS + h) * SEQ) + n) * DIM_HEAD + d] = v;
            } else {
                Cext[(size_t)m * DMODEL + c] = v;
            }
        }
    }
}

// ---------------------------------------------------------------------------
// Flash attention: 1 thread = 1 query row. q[64] and o[64] in registers,
// K/V tiles of 16 rows staged in smem (broadcast reads), online softmax.
// grid: (SEQ/128, BATCH*HEADS), block: 128 threads
// ---------------------------------------------------------------------------
__global__ __launch_bounds__(128)
void attn_kernel(const float* __restrict__ bias)
{
    __shared__ float4 ks[16 * 16];   // [krow][d4]
    __shared__ float4 vs[16 * 16];

    const int tid = threadIdx.x;
    const int bh  = blockIdx.y;
    const int h   = bh & (HEADS - 1);
    const int b   = bh >> 3;
    const int row = blockIdx.x * 128 + tid;

    const float4* __restrict__ Q4 = (const float4*)g_q + ((size_t)bh * SEQ + row) * 16;
    const float4* __restrict__ K4 = (const float4*)g_k + (size_t)bh * SEQ * 16;
    const float4* __restrict__ V4 = (const float4*)g_v + (size_t)bh * SEQ * 16;
    const float*  __restrict__ bp = bias + ((size_t)h * SEQ + row) * SEQ;

    float4 q[16];
#pragma unroll
    for (int i = 0; i < 16; i++) q[i] = Q4[i];

    float4 o[16];
#pragma unroll
    for (int i = 0; i < 16; i++) o[i] = make_float4(0.f, 0.f, 0.f, 0.f);

    float m_run = -1e30f;
    float l_run = 0.f;

    for (int kt = 0; kt < SEQ; kt += 16) {
        __syncthreads();
        // stage 16x64 K and V tiles (256 float4 each, 128 threads -> 2 apiece)
        ks[tid]       = K4[kt * 16 + tid];
        ks[tid + 128] = K4[kt * 16 + 128 + tid];
        vs[tid]       = V4[kt * 16 + tid];
        vs[tid + 128] = V4[kt * 16 + 128 + tid];
        __syncthreads();

        float s[16];
#pragma unroll
        for (int j = 0; j < 16; j++) {
            float sum = 0.f;
#pragma unroll
            for (int d = 0; d < 16; d++) {
                float4 kk = ks[j * 16 + d];
                sum += q[d].x * kk.x + q[d].y * kk.y + q[d].z * kk.z + q[d].w * kk.w;
            }
            s[j] = sum;
        }

        // add positional bias (row-contiguous)
#pragma unroll
        for (int j4 = 0; j4 < 4; j4++) {
            float4 bb = *(const float4*)(bp + kt + j4 * 4);
            s[j4 * 4 + 0] += bb.x;
            s[j4 * 4 + 1] += bb.y;
            s[j4 * 4 + 2] += bb.z;
            s[j4 * 4 + 3] += bb.w;
        }

        float mt = m_run;
#pragma unroll
        for (int j = 0; j < 16; j++) mt = fmaxf(mt, s[j]);

        const float corr = __expf(m_run - mt);
        l_run *= corr;
#pragma unroll
        for (int i = 0; i < 16; i++) {
            o[i].x *= corr; o[i].y *= corr; o[i].z *= corr; o[i].w *= corr;
        }

#pragma unroll
        for (int j = 0; j < 16; j++) {
            const float p = __expf(s[j] - mt);
            l_run += p;
#pragma unroll
            for (int d = 0; d < 16; d++) {
                float4 vv = vs[j * 16 + d];
                o[d].x += p * vv.x;
                o[d].y += p * vv.y;
                o[d].z += p * vv.z;
                o[d].w += p * vv.w;
            }
        }
        m_run = mt;
    }

    const float inv = 1.f / l_run;
    float4* __restrict__ Og = (float4*)g_o + ((size_t)b * SEQ + row) * (DMODEL / 4) + h * 16;
#pragma unroll
    for (int i = 0; i < 16; i++) {
        o[i].x *= inv; o[i].y *= inv; o[i].z *= inv; o[i].w *= inv;
        Og[i] = o[i];
    }
}

// ---------------------------------------------------------------------------
extern "C" void kernel_launch(void* const* d_in, const int* in_sizes, int n_in,
                              void* d_out, int out_size)
{
    const float* query = (const float*)d_in[0];
    const float* bias  = (const float*)d_in[1];
    const float* Wq    = (const float*)d_in[2];
    const float* Wk    = (const float*)d_in[3];
    const float* Wv    = (const float*)d_in[4];
    const float* Wout  = (const float*)d_in[5];
    float* out = (float*)d_out;

    dim3 gemm_grid(DMODEL / 64, M_ROWS / 64);   // (8, 128)
    gemm_kernel<0><<<gemm_grid, 256>>>(query, Wq, nullptr);
    gemm_kernel<1><<<gemm_grid, 256>>>(query, Wk, nullptr);
    gemm_kernel<2><<<gemm_grid, 256>>>(query, Wv, nullptr);

    dim3 attn_grid(SEQ / 128, BATCH * HEADS);   // (16, 32)
    attn_kernel<<<attn_grid, 128>>>(bias);

    gemm_kernel<3><<<gemm_grid, 256>>>(nullptr, Wout, out);
}

// round 2
// speedup vs baseline: 2.5267x; 2.5267x over previous
#include <cuda_runtime.h>

#define HEADS 8
#define DIM_HEAD 64
#define BATCH 4
#define SEQ 2048
#define DMODEL 512
#define M_ROWS (BATCH * SEQ)           // 8192
#define QK_SCALE 0.125f                // 64^-0.5
#define FULLMASK 0xffffffffu

// Scratch (device-global; no allocation allowed)
__device__ float g_q[BATCH * HEADS * SEQ * DIM_HEAD];   // [b,h,n,d], pre-scaled
__device__ float g_k[BATCH * HEADS * SEQ * DIM_HEAD];
__device__ float g_v[BATCH * HEADS * SEQ * DIM_HEAD];
__device__ float g_o[BATCH * SEQ * DMODEL];             // [b,n,h*64+d]

// ---------------------------------------------------------------------------
// tf32 helpers
// ---------------------------------------------------------------------------
__device__ __forceinline__ unsigned f2tf(float x) {
    unsigned u;
    asm("cvt.rna.tf32.f32 %0, %1;" : "=r"(u) : "f"(x));
    return u;
}

__device__ __forceinline__ void mma_tf32(float* c, const unsigned* a, const unsigned* b) {
    asm volatile(
        "mma.sync.aligned.m16n8k8.row.col.f32.tf32.tf32.f32 "
        "{%0,%1,%2,%3}, {%4,%5,%6,%7}, {%8,%9}, {%0,%1,%2,%3};"
        : "+f"(c[0]), "+f"(c[1]), "+f"(c[2]), "+f"(c[3])
        : "r"(a[0]), "r"(a[1]), "r"(a[2]), "r"(a[3]), "r"(b[0]), "r"(b[1]));
}

// ---------------------------------------------------------------------------
// tf32 GEMM: C[8192,512] = A[8192,512] @ W[512,512]
// MODE 0/1/2: A = query, C -> g_q/g_k/g_v split-head (MODE 0 scales by QK_SCALE)
// MODE 3:     A = g_o,   C -> external out
// block 256 thr = 8 warps (4M x 2N), block tile 128x64, warp tile 32x32
// ---------------------------------------------------------------------------
template <int MODE>
__global__ __launch_bounds__(256)
void gemm_tf32(const float* __restrict__ Aext,
               const float* __restrict__ W,
               float* __restrict__ Cext)
{
    __shared__ unsigned As[128][36];   // [m][k+4 pad] -> conflict-free frag reads
    __shared__ unsigned Bs[64][36];    // [n][k+4 pad]

    const float* __restrict__ A = (MODE == 3) ? g_o : Aext;

    const int tid  = threadIdx.x;
    const int warp = tid >> 5, lane = tid & 31;
    const int g = lane >> 2, t = lane & 3;
    const int wm = warp & 3, wn = warp >> 2;
    const int m0 = blockIdx.y * 128;
    const int c0 = blockIdx.x * 64;

    float acc[2][4][4];
#pragma unroll
    for (int i = 0; i < 2; i++)
#pragma unroll
        for (int j = 0; j < 4; j++)
#pragma unroll
            for (int k = 0; k < 4; k++) acc[i][j][k] = 0.f;

    for (int k0 = 0; k0 < DMODEL; k0 += 32) {
        __syncthreads();
        // stage A 128x32 (cvt to tf32), [m][k]
#pragma unroll
        for (int i = 0; i < 4; i++) {
            int f4  = tid + i * 256;       // 0..1023
            int row = f4 >> 3;             // 8 float4 per row
            int c4  = f4 & 7;
            float4 v = *(const float4*)(A + (size_t)(m0 + row) * DMODEL + k0 + c4 * 4);
            uint4 u = make_uint4(f2tf(v.x), f2tf(v.y), f2tf(v.z), f2tf(v.w));
            *(uint4*)&As[row][c4 * 4] = u;
        }
        // stage B 32x64 transposed -> [n][k]
#pragma unroll
        for (int i = 0; i < 2; i++) {
            int f4 = tid + i * 256;        // 0..511
            int kr = f4 >> 4;              // 16 float4 per row of 64
            int c4 = f4 & 15;
            float4 v = *(const float4*)(W + (size_t)(k0 + kr) * DMODEL + c0 + c4 * 4);
            Bs[c4 * 4 + 0][kr] = f2tf(v.x);
            Bs[c4 * 4 + 1][kr] = f2tf(v.y);
            Bs[c4 * 4 + 2][kr] = f2tf(v.z);
            Bs[c4 * 4 + 3][kr] = f2tf(v.w);
        }
        __syncthreads();

#pragma unroll
        for (int ks = 0; ks < 4; ks++) {
            const int kk = ks * 8;
            unsigned af[2][4], bf[4][2];
#pragma unroll
            for (int mt = 0; mt < 2; mt++) {
                int r = wm * 32 + mt * 16;
                af[mt][0] = As[r + g][kk + t];
                af[mt][1] = As[r + g + 8][kk + t];
                af[mt][2] = As[r + g][kk + t + 4];
                af[mt][3] = As[r + g + 8][kk + t + 4];
            }
#pragma unroll
            for (int nt = 0; nt < 4; nt++) {
                int n = wn * 32 + nt * 8;
                bf[nt][0] = Bs[n + g][kk + t];
                bf[nt][1] = Bs[n + g][kk + t + 4];
            }
#pragma unroll
            for (int mt = 0; mt < 2; mt++)
#pragma unroll
                for (int nt = 0; nt < 4; nt++)
                    mma_tf32(acc[mt][nt], af[mt], bf[nt]);
        }
    }

    // epilogue
#pragma unroll
    for (int mt = 0; mt < 2; mt++) {
#pragma unroll
        for (int nt = 0; nt < 4; nt++) {
#pragma unroll
            for (int half = 0; half < 2; half++) {
                int m = m0 + wm * 32 + mt * 16 + g + half * 8;
                int c = c0 + wn * 32 + nt * 8 + 2 * t;
                float v0 = acc[mt][nt][half * 2 + 0];
                float v1 = acc[mt][nt][half * 2 + 1];
                if (MODE == 0) { v0 *= QK_SCALE; v1 *= QK_SCALE; }
                int b = m >> 11, n = m & 2047;
                if (MODE < 3) {
                    int hh = c >> 6, d = c & 63;
                    float* dst = (MODE == 0) ? g_q : (MODE == 1) ? g_k : g_v;
                    *(float2*)&dst[((((size_t)b * HEADS + hh) * SEQ) + n) * DIM_HEAD + d] =
                        make_float2(v0, v1);
                } else {
                    *(float2*)&Cext[(size_t)m * DMODEL + c] = make_float2(v0, v1);
                }
            }
        }
    }
}

// ---------------------------------------------------------------------------
// Flash attention, tf32 mma. Block = 128 query rows (8 warps x 16), key
// chunks of 64. Q frags live in registers; K in smem [key][dh]; V transposed
// [dh][key]. P re-layout C-frag -> A-frag done with quad shuffles (no smem).
// grid: (SEQ/128, BATCH*HEADS), block 256
// ---------------------------------------------------------------------------
__global__ __launch_bounds__(256)
void attn_tf32(const float* __restrict__ bias)
{
    __shared__ unsigned Ks[64][68];   // [key][dh] + pad 4
    __shared__ unsigned Vt[64][68];   // [dh][key] + pad 4

    const int tid  = threadIdx.x;
    const int warp = tid >> 5, lane = tid & 31;
    const int g = lane >> 2, t = lane & 3;
    const int bh = blockIdx.y;
    const int h  = bh & (HEADS - 1);
    const int b  = bh >> 3;
    const int qw = blockIdx.x * 128 + warp * 16;   // warp's first query row

    const float* __restrict__ Qg = g_q + (size_t)bh * SEQ * DIM_HEAD;
    const float* __restrict__ Kg = g_k + (size_t)bh * SEQ * DIM_HEAD;
    const float* __restrict__ Vg = g_v + (size_t)bh * SEQ * DIM_HEAD;
    const float* __restrict__ bp0 = bias + ((size_t)h * SEQ + qw + g) * SEQ;
    const float* __restrict__ bp1 = bias + ((size_t)h * SEQ + qw + g + 8) * SEQ;

    // Q A-frags for 8 k-steps (Dh=64), loaded once
    unsigned qa[8][4];
#pragma unroll
    for (int s = 0; s < 8; s++) {
        qa[s][0] = f2tf(Qg[(size_t)(qw + g)     * DIM_HEAD + 8 * s + t]);
        qa[s][1] = f2tf(Qg[(size_t)(qw + g + 8) * DIM_HEAD + 8 * s + t]);
        qa[s][2] = f2tf(Qg[(size_t)(qw + g)     * DIM_HEAD + 8 * s + t + 4]);
        qa[s][3] = f2tf(Qg[(size_t)(qw + g + 8) * DIM_HEAD + 8 * s + t + 4]);
    }

    float o[8][4];
#pragma unroll
    for (int i = 0; i < 8; i++)
#pragma unroll
        for (int j = 0; j < 4; j++) o[i][j] = 0.f;

    float m0r = -1e30f, m1r = -1e30f, l0 = 0.f, l1 = 0.f;

    for (int kt = 0; kt < SEQ; kt += 64) {
        __syncthreads();
        // stage K [key][dh] and V transposed [dh][key], cvt to tf32
#pragma unroll
        for (int i = 0; i < 4; i++) {
            int f4  = tid + i * 256;
            int row = f4 >> 4;     // 16 float4 per 64-wide row
            int c4  = f4 & 15;
            float4 v = *(const float4*)(Kg + (size_t)(kt + row) * DIM_HEAD + c4 * 4);
            uint4 u = make_uint4(f2tf(v.x), f2tf(v.y), f2tf(v.z), f2tf(v.w));
            *(uint4*)&Ks[row][c4 * 4] = u;
            float4 w = *(const float4*)(Vg + (size_t)(kt + row) * DIM_HEAD + c4 * 4);
            Vt[c4 * 4 + 0][row] = f2tf(w.x);
            Vt[c4 * 4 + 1][row] = f2tf(w.y);
            Vt[c4 * 4 + 2][row] = f2tf(w.z);
            Vt[c4 * 4 + 3][row] = f2tf(w.w);
        }
        __syncthreads();

        // S = Q K^T  (scores; Q pre-scaled)
        float s[8][4];
#pragma unroll
        for (int i = 0; i < 8; i++)
#pragma unroll
            for (int j = 0; j < 4; j++) s[i][j] = 0.f;

#pragma unroll
        for (int ks = 0; ks < 8; ks++) {
#pragma unroll
            for (int nt = 0; nt < 8; nt++) {
                unsigned bf[2];
                bf[0] = Ks[nt * 8 + g][ks * 8 + t];
                bf[1] = Ks[nt * 8 + g][ks * 8 + t + 4];
                mma_tf32(s[nt], qa[ks], bf);
            }
        }

        // add bias, running row max
        float mx0 = m0r, mx1 = m1r;
#pragma unroll
        for (int nt = 0; nt < 8; nt++) {
            float2 bb0 = *(const float2*)(bp0 + kt + nt * 8 + 2 * t);
            float2 bb1 = *(const float2*)(bp1 + kt + nt * 8 + 2 * t);
            s[nt][0] += bb0.x; s[nt][1] += bb0.y;
            s[nt][2] += bb1.x; s[nt][3] += bb1.y;
            mx0 = fmaxf(mx0, fmaxf(s[nt][0], s[nt][1]));
            mx1 = fmaxf(mx1, fmaxf(s[nt][2], s[nt][3]));
        }
        mx0 = fmaxf(mx0, __shfl_xor_sync(FULLMASK, mx0, 1));
        mx0 = fmaxf(mx0, __shfl_xor_sync(FULLMASK, mx0, 2));
        mx1 = fmaxf(mx1, __shfl_xor_sync(FULLMASK, mx1, 1));
        mx1 = fmaxf(mx1, __shfl_xor_sync(FULLMASK, mx1, 2));

        const float cr0 = __expf(m0r - mx0);
        const float cr1 = __expf(m1r - mx1);
        m0r = mx0; m1r = mx1;

        float ls0 = 0.f, ls1 = 0.f;
#pragma unroll
        for (int nt = 0; nt < 8; nt++) {
            s[nt][0] = __expf(s[nt][0] - mx0);
            s[nt][1] = __expf(s[nt][1] - mx0);
            s[nt][2] = __expf(s[nt][2] - mx1);
            s[nt][3] = __expf(s[nt][3] - mx1);
            ls0 += s[nt][0] + s[nt][1];
            ls1 += s[nt][2] + s[nt][3];
            o[nt][0] *= cr0; o[nt][1] *= cr0;
            o[nt][2] *= cr1; o[nt][3] *= cr1;
        }
        ls0 += __shfl_xor_sync(FULLMASK, ls0, 1);
        ls0 += __shfl_xor_sync(FULLMASK, ls0, 2);
        ls1 += __shfl_xor_sync(FULLMASK, ls1, 1);
        ls1 += __shfl_xor_sync(FULLMASK, ls1, 2);
        l0 = l0 * cr0 + ls0;
        l1 = l1 * cr1 + ls1;

        // O += P @ V : re-layout P (C-frag -> A-frag) via quad shuffles
#pragma unroll
        for (int j = 0; j < 8; j++) {          // k-step over keys == P n-tile j
            const int l0q = (lane & ~3) | (t >> 1);
            const int l1q = (lane & ~3) | (2 + (t >> 1));
            float v00 = __shfl_sync(FULLMASK, s[j][0], l0q);
            float v01 = __shfl_sync(FULLMASK, s[j][1], l0q);
            float v02 = __shfl_sync(FULLMASK, s[j][2], l0q);
            float v03 = __shfl_sync(FULLMASK, s[j][3], l0q);
            float v10 = __shfl_sync(FULLMASK, s[j][0], l1q);
            float v11 = __shfl_sync(FULLMASK, s[j][1], l1q);
            float v12 = __shfl_sync(FULLMASK, s[j][2], l1q);
            float v13 = __shfl_sync(FULLMASK, s[j][3], l1q);
            const bool odd = t & 1;
            unsigned pa[4];
            pa[0] = f2tf(odd ? v01 : v00);
            pa[1] = f2tf(odd ? v03 : v02);
            pa[2] = f2tf(odd ? v11 : v10);
            pa[3] = f2tf(odd ? v13 : v12);
#pragma unroll
            for (int nt = 0; nt < 8; nt++) {
                unsigned bf[2];
                bf[0] = Vt[nt * 8 + g][j * 8 + t];
                bf[1] = Vt[nt * 8 + g][j * 8 + t + 4];
                mma_tf32(o[nt], pa, bf);
            }
        }
    }

    // normalize + write to g_o [b][n][h*64+d]
    const float inv0 = 1.f / l0, inv1 = 1.f / l1;
    float* __restrict__ Og = g_o + ((size_t)b * SEQ + qw) * DMODEL + h * DIM_HEAD;
#pragma unroll
    for (int nt = 0; nt < 8; nt++) {
        *(float2*)&Og[(size_t)g * DMODEL + nt * 8 + 2 * t] =
            make_float2(o[nt][0] * inv0, o[nt][1] * inv0);
        *(float2*)&Og[(size_t)(g + 8) * DMODEL + nt * 8 + 2 * t] =
            make_float2(o[nt][2] * inv1, o[nt][3] * inv1);
    }
}

// ---------------------------------------------------------------------------
extern "C" void kernel_launch(void* const* d_in, const int* in_sizes, int n_in,
                              void* d_out, int out_size)
{
    const float* query = (const float*)d_in[0];
    const float* bias  = (const float*)d_in[1];
    const float* Wq    = (const float*)d_in[2];
    const float* Wk    = (const float*)d_in[3];
    const float* Wv    = (const float*)d_in[4];
    const float* Wout  = (const float*)d_in[5];
    float* out = (float*)d_out;

    dim3 gemm_grid(DMODEL / 64, M_ROWS / 128);   // (8, 64)
    gemm_tf32<0><<<gemm_grid, 256>>>(query, Wq, nullptr);
    gemm_tf32<1><<<gemm_grid, 256>>>(query, Wk, nullptr);
    gemm_tf32<2><<<gemm_grid, 256>>>(query, Wv, nullptr);

    dim3 attn_grid(SEQ / 128, BATCH * HEADS);    // (16, 32)
    attn_tf32<<<attn_grid, 256>>>(bias);

    gemm_tf32<3><<<gemm_grid, 256>>>(nullptr, Wout, out);
}

// round 4
// speedup vs baseline: 2.5289x; 1.0008x over previous
#include <cuda_runtime.h>

#define HEADS 8
#define DIM_HEAD 64
#define BATCH 4
#define SEQ 2048
#define DMODEL 512
#define M_ROWS (BATCH * SEQ)           // 8192
#define QK_SCALE 0.125f                // 64^-0.5
#define FULLMASK 0xffffffffu
#define PERM(c) ((((c) & 7) << 3) | ((c) >> 3))   // k-contiguous fragment perm (64-wide)

// Scratch (device-global; no allocation allowed)
__device__ float g_q[BATCH * HEADS * SEQ * DIM_HEAD];   // [b,h,n,d], pre-scaled
__device__ float g_k[BATCH * HEADS * SEQ * DIM_HEAD];
__device__ float g_v[BATCH * HEADS * SEQ * DIM_HEAD];
__device__ float g_o[BATCH * SEQ * DMODEL];             // [b,n,h*64+d]

__device__ __forceinline__ unsigned f2tf(float x) {
    unsigned u;
    asm("cvt.rna.tf32.f32 %0, %1;" : "=r"(u) : "f"(x));
    return u;
}

__device__ __forceinline__ void mma_tf32(float* c, const unsigned* a, const unsigned* b) {
    asm volatile(
        "mma.sync.aligned.m16n8k8.row.col.f32.tf32.tf32.f32 "
        "{%0,%1,%2,%3}, {%4,%5,%6,%7}, {%8,%9}, {%0,%1,%2,%3};"
        : "+f"(c[0]), "+f"(c[1]), "+f"(c[2]), "+f"(c[3])
        : "r"(a[0]), "r"(a[1]), "r"(a[2]), "r"(a[3]), "r"(b[0]), "r"(b[1]));
}

// Load one smem row's fragment words for all 8 k-steps: 4x LDS.128.
// a[ks] = word at [t*8+ks] (k = ks*8+t), b[ks] = word at [(t+4)*8+ks] (k = ks*8+t+4)
struct Frag8 { unsigned a[8]; unsigned b[8]; };
__device__ __forceinline__ void load_frag8(const unsigned* base, int t, Frag8& f) {
    const uint4* p = (const uint4*)base;
    uint4 x0 = p[t * 2], x1 = p[t * 2 + 1];
    uint4 y0 = p[(t + 4) * 2], y1 = p[(t + 4) * 2 + 1];
    f.a[0] = x0.x; f.a[1] = x0.y; f.a[2] = x0.z; f.a[3] = x0.w;
    f.a[4] = x1.x; f.a[5] = x1.y; f.a[6] = x1.z; f.a[7] = x1.w;
    f.b[0] = y0.x; f.b[1] = y0.y; f.b[2] = y0.z; f.b[3] = y0.w;
    f.b[4] = y1.x; f.b[5] = y1.y; f.b[6] = y1.z; f.b[7] = y1.w;
}

// ---------------------------------------------------------------------------
// tf32 GEMM: C[8192,512] = A[8192,512] @ W[512,512]
// block 128 thr = 4 warps (2M x 2N), block tile 64x64, warp tile 32x32, K-block 64
// MODE 0/1/2: A = query, C -> g_q/g_k/g_v split-head (MODE 0 scales by QK_SCALE)
// MODE 3:     A = g_o,   C -> external out
// ---------------------------------------------------------------------------
template <int MODE>
__global__ __launch_bounds__(128)
void gemm_tf32(const float* __restrict__ Aext,
               const float* __restrict__ W,
               float* __restrict__ Cext)
{
    __shared__ unsigned As[64][68];   // [m][perm(k)]
    __shared__ unsigned Bs[64][68];   // [n][perm(k)]

    const float* __restrict__ A = (MODE == 3) ? g_o : Aext;

    const int tid  = threadIdx.x;
    const int warp = tid >> 5, lane = tid & 31;
    const int g = lane >> 2, t = lane & 3;
    const int wm = warp & 1, wn = warp >> 1;
    const int m0 = blockIdx.y * 64;
    const int c0 = blockIdx.x * 64;

    float acc[2][4][4];
#pragma unroll
    for (int i = 0; i < 2; i++)
#pragma unroll
        for (int j = 0; j < 4; j++)
#pragma unroll
            for (int k = 0; k < 4; k++) acc[i][j][k] = 0.f;

    // prefetch regs: 8 float4 for A tile, 8 for B tile
    float4 pa[8], pb[8];
#pragma unroll
    for (int i = 0; i < 8; i++) {
        int f4 = tid + i * 128;
        int row = f4 >> 4, q = f4 & 15;
        pa[i] = *(const float4*)(A + (size_t)(m0 + row) * DMODEL + q * 4);
        pb[i] = *(const float4*)(W + (size_t)row * DMODEL + c0 + q * 4);
    }

    for (int k0 = 0; k0 < DMODEL; k0 += 64) {
        __syncthreads();
#pragma unroll
        for (int i = 0; i < 8; i++) {
            int f4 = tid + i * 128;
            int row = f4 >> 4, q = f4 & 15;
            As[row][PERM(4 * q + 0)] = f2tf(pa[i].x);
            As[row][PERM(4 * q + 1)] = f2tf(pa[i].y);
            As[row][PERM(4 * q + 2)] = f2tf(pa[i].z);
            As[row][PERM(4 * q + 3)] = f2tf(pa[i].w);
            // B staging: row = k index, q*4+j = n index
            Bs[4 * q + 0][PERM(row)] = f2tf(pb[i].x);
            Bs[4 * q + 1][PERM(row)] = f2tf(pb[i].y);
            Bs[4 * q + 2][PERM(row)] = f2tf(pb[i].z);
            Bs[4 * q + 3][PERM(row)] = f2tf(pb[i].w);
        }
        __syncthreads();

        if (k0 + 64 < DMODEL) {
#pragma unroll
            for (int i = 0; i < 8; i++) {
                int f4 = tid + i * 128;
                int row = f4 >> 4, q = f4 & 15;
                pa[i] = *(const float4*)(A + (size_t)(m0 + row) * DMODEL + k0 + 64 + q * 4);
                pb[i] = *(const float4*)(W + (size_t)(k0 + 64 + row) * DMODEL + c0 + q * 4);
            }
        }

        Frag8 fa[4];
        load_frag8(&As[wm * 32 + g][0],      t, fa[0]);
        load_frag8(&As[wm * 32 + 8 + g][0],  t, fa[1]);
        load_frag8(&As[wm * 32 + 16 + g][0], t, fa[2]);
        load_frag8(&As[wm * 32 + 24 + g][0], t, fa[3]);

#pragma unroll
        for (int nt = 0; nt < 4; nt++) {
            Frag8 fb;
            load_frag8(&Bs[wn * 32 + nt * 8 + g][0], t, fb);
#pragma unroll
            for (int ks = 0; ks < 8; ks++) {
                unsigned bfr[2] = {fb.a[ks], fb.b[ks]};
                unsigned af0[4] = {fa[0].a[ks], fa[1].a[ks], fa[0].b[ks], fa[1].b[ks]};
                mma_tf32(acc[0][nt], af0, bfr);
                unsigned af1[4] = {fa[2].a[ks], fa[3].a[ks], fa[2].b[ks], fa[3].b[ks]};
                mma_tf32(acc[1][nt], af1, bfr);
            }
        }
    }

    // epilogue
#pragma unroll
    for (int mt = 0; mt < 2; mt++) {
#pragma unroll
        for (int nt = 0; nt < 4; nt++) {
#pragma unroll
            for (int half = 0; half < 2; half++) {
                int m = m0 + wm * 32 + mt * 16 + g + half * 8;
                int c = c0 + wn * 32 + nt * 8 + 2 * t;
                float v0 = acc[mt][nt][half * 2 + 0];
                float v1 = acc[mt][nt][half * 2 + 1];
                if (MODE == 0) { v0 *= QK_SCALE; v1 *= QK_SCALE; }
                int b = m >> 11, n = m & 2047;
                if (MODE < 3) {
                    int hh = c >> 6, d = c & 63;
                    float* dst = (MODE == 0) ? g_q : (MODE == 1) ? g_k : g_v;
                    *(float2*)&dst[((((size_t)b * HEADS + hh) * SEQ) + n) * DIM_HEAD + d] =
                        make_float2(v0, v1);
                } else {
                    *(float2*)&Cext[(size_t)m * DMODEL + c] = make_float2(v0, v1);
                }
            }
        }
    }
}

// ---------------------------------------------------------------------------
// Flash attention, tf32 mma, permuted smem layouts + register double-buffer.
// Block = 128 query rows (8 warps x 16), key chunks of 64.
// grid: (SEQ/128, BATCH*HEADS), block 256
// ---------------------------------------------------------------------------
__global__ __launch_bounds__(256)
void attn_tf32(const float* __restrict__ bias)
{
    __shared__ unsigned Ks[64][68];   // [key][perm(dh)]
    __shared__ unsigned Vt[64][68];   // [dh][perm(key)]

    const int tid  = threadIdx.x;
    const int warp = tid >> 5, lane = tid & 31;
    const int g = lane >> 2, t = lane & 3;
    const int bh = blockIdx.y;
    const int h  = bh & (HEADS - 1);
    const int b  = bh >> 3;
    const int qw = blockIdx.x * 128 + warp * 16;

    const float* __restrict__ Qg = g_q + (size_t)bh * SEQ * DIM_HEAD;
    const float* __restrict__ Kg = g_k + (size_t)bh * SEQ * DIM_HEAD;
    const float* __restrict__ Vg = g_v + (size_t)bh * SEQ * DIM_HEAD;
    const float* __restrict__ bp0 = bias + ((size_t)h * SEQ + qw + g) * SEQ;
    const float* __restrict__ bp1 = bias + ((size_t)h * SEQ + qw + g + 8) * SEQ;

    // Q A-frags for 8 k-steps, loaded once
    unsigned qa[8][4];
#pragma unroll
    for (int s = 0; s < 8; s++) {
        qa[s][0] = f2tf(Qg[(size_t)(qw + g)     * DIM_HEAD + 8 * s + t]);
        qa[s][1] = f2tf(Qg[(size_t)(qw + g + 8) * DIM_HEAD + 8 * s + t]);
        qa[s][2] = f2tf(Qg[(size_t)(qw + g)     * DIM_HEAD + 8 * s + t + 4]);
        qa[s][3] = f2tf(Qg[(size_t)(qw + g + 8) * DIM_HEAD + 8 * s + t + 4]);
    }

    float o[8][4];
#pragma unroll
    for (int i = 0; i < 8; i++)
#pragma unroll
        for (int j = 0; j < 4; j++) o[i][j] = 0.f;

    float m0r = -1e30f, m1r = -1e30f, l0 = 0.f, l1 = 0.f;

    // prefetch regs for chunk 0
    float4 pk[4], pv[4];
#pragma unroll
    for (int i = 0; i < 4; i++) {
        int f4 = tid + i * 256;
        int row = f4 >> 4, q = f4 & 15;
        pk[i] = *(const float4*)(Kg + (size_t)row * DIM_HEAD + q * 4);
        pv[i] = *(const float4*)(Vg + (size_t)row * DIM_HEAD + q * 4);
    }

    for (int kt = 0; kt < SEQ; kt += 64) {
        __syncthreads();
#pragma unroll
        for (int i = 0; i < 4; i++) {
            int f4 = tid + i * 256;
            int row = f4 >> 4, q = f4 & 15;
            Ks[row][PERM(4 * q + 0)] = f2tf(pk[i].x);
            Ks[row][PERM(4 * q + 1)] = f2tf(pk[i].y);
            Ks[row][PERM(4 * q + 2)] = f2tf(pk[i].z);
            Ks[row][PERM(4 * q + 3)] = f2tf(pk[i].w);
            Vt[4 * q + 0][PERM(row)] = f2tf(pv[i].x);
            Vt[4 * q + 1][PERM(row)] = f2tf(pv[i].y);
            Vt[4 * q + 2][PERM(row)] = f2tf(pv[i].z);
            Vt[4 * q + 3][PERM(row)] = f2tf(pv[i].w);
        }
        __syncthreads();

        if (kt + 64 < SEQ) {
#pragma unroll
            for (int i = 0; i < 4; i++) {
                int f4 = tid + i * 256;
                int row = f4 >> 4, q = f4 & 15;
                pk[i] = *(const float4*)(Kg + (size_t)(kt + 64 + row) * DIM_HEAD + q * 4);
                pv[i] = *(const float4*)(Vg + (size_t)(kt + 64 + row) * DIM_HEAD + q * 4);
            }
        }

        // S = Q K^T
        float s[8][4];
#pragma unroll
        for (int i = 0; i < 8; i++)
#pragma unroll
            for (int j = 0; j < 4; j++) s[i][j] = 0.f;

#pragma unroll
        for (int ntp = 0; ntp < 4; ntp++) {
            Frag8 f0, f1;
            load_frag8(&Ks[ntp * 16 + g][0],     t, f0);
            load_frag8(&Ks[ntp * 16 + 8 + g][0], t, f1);
#pragma unroll
            for (int ks = 0; ks < 8; ks++) {
                unsigned bf0[2] = {f0.a[ks], f0.b[ks]};
                mma_tf32(s[2 * ntp], qa[ks], bf0);
                unsigned bf1[2] = {f1.a[ks], f1.b[ks]};
                mma_tf32(s[2 * ntp + 1], qa[ks], bf1);
            }
        }

        // bias + running max
        float mx0 = m0r, mx1 = m1r;
#pragma unroll
        for (int nt = 0; nt < 8; nt++) {
            float2 bb0 = *(const float2*)(bp0 + kt + nt * 8 + 2 * t);
            float2 bb1 = *(const float2*)(bp1 + kt + nt * 8 + 2 * t);
            s[nt][0] += bb0.x; s[nt][1] += bb0.y;
            s[nt][2] += bb1.x; s[nt][3] += bb1.y;
            mx0 = fmaxf(mx0, fmaxf(s[nt][0], s[nt][1]));
            mx1 = fmaxf(mx1, fmaxf(s[nt][2], s[nt][3]));
        }
        mx0 = fmaxf(mx0, __shfl_xor_sync(FULLMASK, mx0, 1));
        mx0 = fmaxf(mx0, __shfl_xor_sync(FULLMASK, mx0, 2));
        mx1 = fmaxf(mx1, __shfl_xor_sync(FULLMASK, mx1, 1));
        mx1 = fmaxf(mx1, __shfl_xor_sync(FULLMASK, mx1, 2));

        const float cr0 = __expf(m0r - mx0);
        const float cr1 = __expf(m1r - mx1);
        m0r = mx0; m1r = mx1;

        float ls0 = 0.f, ls1 = 0.f;
#pragma unroll
        for (int nt = 0; nt < 8; nt++) {
            s[nt][0] = __expf(s[nt][0] - mx0);
            s[nt][1] = __expf(s[nt][1] - mx0);
            s[nt][2] = __expf(s[nt][2] - mx1);
            s[nt][3] = __expf(s[nt][3] - mx1);
            ls0 += s[nt][0] + s[nt][1];
            ls1 += s[nt][2] + s[nt][3];
            o[nt][0] *= cr0; o[nt][1] *= cr0;
            o[nt][2] *= cr1; o[nt][3] *= cr1;
        }
        ls0 += __shfl_xor_sync(FULLMASK, ls0, 1);
        ls0 += __shfl_xor_sync(FULLMASK, ls0, 2);
        ls1 += __shfl_xor_sync(FULLMASK, ls1, 1);
        ls1 += __shfl_xor_sync(FULLMASK, ls1, 2);
        l0 = l0 * cr0 + ls0;
        l1 = l1 * cr1 + ls1;

        // relayout P: C-frag -> A-frag via quad shuffles (all 8 j first)
        unsigned pa_[8][4];
        const int l0q = (lane & ~3) | (t >> 1);
        const int l1q = (lane & ~3) | (2 + (t >> 1));
        const bool odd = t & 1;
#pragma unroll
        for (int j = 0; j < 8; j++) {
            float v00 = __shfl_sync(FULLMASK, s[j][0], l0q);
            float v01 = __shfl_sync(FULLMASK, s[j][1], l0q);
            float v02 = __shfl_sync(FULLMASK, s[j][2], l0q);
            float v03 = __shfl_sync(FULLMASK, s[j][3], l0q);
            float v10 = __shfl_sync(FULLMASK, s[j][0], l1q);
            float v11 = __shfl_sync(FULLMASK, s[j][1], l1q);
            float v12 = __shfl_sync(FULLMASK, s[j][2], l1q);
            float v13 = __shfl_sync(FULLMASK, s[j][3], l1q);
            pa_[j][0] = f2tf(odd ? v01 : v00);
            pa_[j][1] = f2tf(odd ? v03 : v02);
            pa_[j][2] = f2tf(odd ? v11 : v10);
            pa_[j][3] = f2tf(odd ? v13 : v12);
        }

        // O += P @ V
#pragma unroll
        for (int ntp = 0; ntp < 4; ntp++) {
            Frag8 f0, f1;
            load_frag8(&Vt[ntp * 16 + g][0],     t, f0);
            load_frag8(&Vt[ntp * 16 + 8 + g][0], t, f1);
#pragma unroll
            for (int j = 0; j < 8; j++) {
                unsigned bf0[2] = {f0.a[j], f0.b[j]};
                mma_tf32(o[2 * ntp], pa_[j], bf0);
                unsigned bf1[2] = {f1.a[j], f1.b[j]};
                mma_tf32(o[2 * ntp + 1], pa_[j], bf1);
            }
        }
    }

    // normalize + write to g_o [b][n][h*64+d]
    const float inv0 = 1.f / l0, inv1 = 1.f / l1;
    float* __restrict__ Og = g_o + ((size_t)b * SEQ + qw) * DMODEL + h * DIM_HEAD;
#pragma unroll
    for (int nt = 0; nt < 8; nt++) {
        *(float2*)&Og[(size_t)g * DMODEL + nt * 8 + 2 * t] =
            make_float2(o[nt][0] * inv0, o[nt][1] * inv0);
        *(float2*)&Og[(size_t)(g + 8) * DMODEL + nt * 8 + 2 * t] =
            make_float2(o[nt][2] * inv1, o[nt][3] * inv1);
    }
}

// ---------------------------------------------------------------------------
extern "C" void kernel_launch(void* const* d_in, const int* in_sizes, int n_in,
                              void* d_out, int out_size)
{
    const float* query = (const float*)d_in[0];
    const float* bias  = (const float*)d_in[1];
    const float* Wq    = (const float*)d_in[2];
    const float* Wk    = (const float*)d_in[3];
    const float* Wv    = (const float*)d_in[4];
    const float* Wout  = (const float*)d_in[5];
    float* out = (float*)d_out;

    dim3 gemm_grid(DMODEL / 64, M_ROWS / 64);    // (8, 128)
    gemm_tf32<0><<<gemm_grid, 128>>>(query, Wq, nullptr);
    gemm_tf32<1><<<gemm_grid, 128>>>(query, Wk, nullptr);
    gemm_tf32<2><<<gemm_grid, 128>>>(query, Wv, nullptr);

    dim3 attn_grid(SEQ / 128, BATCH * HEADS);    // (16, 32)
    attn_tf32<<<attn_grid, 256>>>(bias);

    gemm_tf32<3><<<gemm_grid, 128>>>(nullptr, Wout, out);
}

// round 6
// speedup vs baseline: 2.9453x; 1.1647x over previous
#include <cuda_runtime.h>

#define HEADS 8
#define DIM_HEAD 64
#define BATCH 4
#define SEQ 2048
#define DMODEL 512
#define M_ROWS (BATCH * SEQ)           // 8192
#define QK_SCALE 0.125f                // 64^-0.5
#define FULLMASK 0xffffffffu
#define PERM(c) ((((c) & 7) << 3) | ((c) >> 3))   // k-contiguous fragment perm (64-wide)

// Scratch (device-global; no allocation allowed)
// g_q: [b,h,n,d]      pre-scaled by QK_SCALE, tf32-rounded
// g_k: [b,h,n,PERM(d)] tf32-rounded, d-permuted
// g_v: [b,h,d, (n&~63)+PERM(n&63)]  tf32-rounded, transposed, key-permuted
// g_o: [b,n,h*64+d]   fp32
__device__ float g_q[BATCH * HEADS * SEQ * DIM_HEAD];
__device__ float g_k[BATCH * HEADS * SEQ * DIM_HEAD];
__device__ float g_v[BATCH * HEADS * SEQ * DIM_HEAD];
__device__ float g_o[BATCH * SEQ * DMODEL];

__device__ __forceinline__ unsigned f2tf(float x) {
    unsigned u;
    asm("cvt.rna.tf32.f32 %0, %1;" : "=r"(u) : "f"(x));
    return u;
}
__device__ __forceinline__ float roundtf(float x) { return __uint_as_float(f2tf(x)); }

__device__ __forceinline__ void mma_tf32(float* c, const unsigned* a, const unsigned* b) {
    asm volatile(
        "mma.sync.aligned.m16n8k8.row.col.f32.tf32.tf32.f32 "
        "{%0,%1,%2,%3}, {%4,%5,%6,%7}, {%8,%9}, {%0,%1,%2,%3};"
        : "+f"(c[0]), "+f"(c[1]), "+f"(c[2]), "+f"(c[3])
        : "r"(a[0]), "r"(a[1]), "r"(a[2]), "r"(a[3]), "r"(b[0]), "r"(b[1]));
}

// Load one smem row's fragment words for all 8 k-steps: 4x LDS.128.
struct Frag8 { unsigned a[8]; unsigned b[8]; };
__device__ __forceinline__ void load_frag8(const unsigned* base, int t, Frag8& f) {
    const uint4* p = (const uint4*)base;
    uint4 x0 = p[t * 2], x1 = p[t * 2 + 1];
    uint4 y0 = p[(t + 4) * 2], y1 = p[(t + 4) * 2 + 1];
    f.a[0] = x0.x; f.a[1] = x0.y; f.a[2] = x0.z; f.a[3] = x0.w;
    f.a[4] = x1.x; f.a[5] = x1.y; f.a[6] = x1.z; f.a[7] = x1.w;
    f.b[0] = y0.x; f.b[1] = y0.y; f.b[2] = y0.z; f.b[3] = y0.w;
    f.b[4] = y1.x; f.b[5] = y1.y; f.b[6] = y1.z; f.b[7] = y1.w;
}

// ---------------------------------------------------------------------------
// Fused QKV tf32 GEMM (R2-proven body): C = query @ W{q,k,v} selected by z.
// block 256 thr = 8 warps (4M x 2N), block tile 128x64, warp 32x32, K-step 32.
// ---------------------------------------------------------------------------
__global__ __launch_bounds__(256)
void gemm_qkv(const float* __restrict__ Aq,
              const float* __restrict__ Wq,
              const float* __restrict__ Wk,
              const float* __restrict__ Wv)
{
    __shared__ unsigned As[128][36];   // [m][k+4 pad]
    __shared__ unsigned Bs[64][36];    // [n][k+4 pad]

    const int z = blockIdx.z;
    const float* __restrict__ W = (z == 0) ? Wq : (z == 1) ? Wk : Wv;
    const float* __restrict__ A = Aq;

    const int tid  = threadIdx.x;
    const int warp = tid >> 5, lane = tid & 31;
    const int g = lane >> 2, t = lane & 3;
    const int wm = warp & 3, wn = warp >> 2;
    const int m0 = blockIdx.y * 128;
    const int c0 = blockIdx.x * 64;

    float acc[2][4][4];
#pragma unroll
    for (int i = 0; i < 2; i++)
#pragma unroll
        for (int j = 0; j < 4; j++)
#pragma unroll
            for (int k = 0; k < 4; k++) acc[i][j][k] = 0.f;

    for (int k0 = 0; k0 < DMODEL; k0 += 32) {
        __syncthreads();
#pragma unroll
        for (int i = 0; i < 4; i++) {
            int f4  = tid + i * 256;
            int row = f4 >> 3;
            int c4  = f4 & 7;
            float4 v = *(const float4*)(A + (size_t)(m0 + row) * DMODEL + k0 + c4 * 4);
            uint4 u = make_uint4(f2tf(v.x), f2tf(v.y), f2tf(v.z), f2tf(v.w));
            *(uint4*)&As[row][c4 * 4] = u;
        }
#pragma unroll
        for (int i = 0; i < 2; i++) {
            int f4 = tid + i * 256;
            int kr = f4 >> 4;
            int c4 = f4 & 15;
            float4 v = *(const float4*)(W + (size_t)(k0 + kr) * DMODEL + c0 + c4 * 4);
            Bs[c4 * 4 + 0][kr] = f2tf(v.x);
            Bs[c4 * 4 + 1][kr] = f2tf(v.y);
            Bs[c4 * 4 + 2][kr] = f2tf(v.z);
            Bs[c4 * 4 + 3][kr] = f2tf(v.w);
        }
        __syncthreads();

#pragma unroll
        for (int ks = 0; ks < 4; ks++) {
            const int kk = ks * 8;
            unsigned af[2][4], bf[4][2];
#pragma unroll
            for (int mt = 0; mt < 2; mt++) {
                int r = wm * 32 + mt * 16;
                af[mt][0] = As[r + g][kk + t];
                af[mt][1] = As[r + g + 8][kk + t];
                af[mt][2] = As[r + g][kk + t + 4];
                af[mt][3] = As[r + g + 8][kk + t + 4];
            }
#pragma unroll
            for (int nt = 0; nt < 4; nt++) {
                int n = wn * 32 + nt * 8;
                bf[nt][0] = Bs[n + g][kk + t];
                bf[nt][1] = Bs[n + g][kk + t + 4];
            }
#pragma unroll
            for (int mt = 0; mt < 2; mt++)
#pragma unroll
                for (int nt = 0; nt < 4; nt++)
                    mma_tf32(acc[mt][nt], af[mt], bf[nt]);
        }
    }

    // epilogue: pre-rounded, per-destination layouts
#pragma unroll
    for (int mt = 0; mt < 2; mt++) {
#pragma unroll
        for (int nt = 0; nt < 4; nt++) {
#pragma unroll
            for (int half = 0; half < 2; half++) {
                int m = m0 + wm * 32 + mt * 16 + g + half * 8;
                int c = c0 + wn * 32 + nt * 8 + 2 * t;
                float v0 = acc[mt][nt][half * 2 + 0];
                float v1 = acc[mt][nt][half * 2 + 1];
                int b = m >> 11, n = m & 2047;
                int hh = c >> 6, d = c & 63;
                size_t bh = (size_t)b * HEADS + hh;
                if (z == 0) {
                    *(float2*)&g_q[(bh * SEQ + n) * DIM_HEAD + d] =
                        make_float2(roundtf(v0 * QK_SCALE), roundtf(v1 * QK_SCALE));
                } else if (z == 1) {
                    float* dst = &g_k[(bh * SEQ + n) * DIM_HEAD];
                    dst[PERM(d)]     = roundtf(v0);
                    dst[PERM(d + 1)] = roundtf(v1);
                } else {
                    int np = (n & ~63) + PERM(n & 63);
                    g_v[(bh * DIM_HEAD + d) * SEQ + np]     = roundtf(v0);
                    g_v[(bh * DIM_HEAD + d + 1) * SEQ + np] = roundtf(v1);
                }
            }
        }
    }
}

// ---------------------------------------------------------------------------
// Output GEMM (MODE3, R2 body): out = g_o @ Wout
// ---------------------------------------------------------------------------
__global__ __launch_bounds__(256)
void gemm_out(const float* __restrict__ W, float* __restrict__ Cext)
{
    __shared__ unsigned As[128][36];
    __shared__ unsigned Bs[64][36];

    const float* __restrict__ A = g_o;
    const int tid  = threadIdx.x;
    const int warp = tid >> 5, lane = tid & 31;
    const int g = lane >> 2, t = lane & 3;
    const int wm = warp & 3, wn = warp >> 2;
    const int m0 = blockIdx.y * 128;
    const int c0 = blockIdx.x * 64;

    float acc[2][4][4];
#pragma unroll
    for (int i = 0; i < 2; i++)
#pragma unroll
        for (int j = 0; j < 4; j++)
#pragma unroll
            for (int k = 0; k < 4; k++) acc[i][j][k] = 0.f;

    for (int k0 = 0; k0 < DMODEL; k0 += 32) {
        __syncthreads();
#pragma unroll
        for (int i = 0; i < 4; i++) {
            int f4  = tid + i * 256;
            int row = f4 >> 3;
            int c4  = f4 & 7;
            float4 v = *(const float4*)(A + (size_t)(m0 + row) * DMODEL + k0 + c4 * 4);
            uint4 u = make_uint4(f2tf(v.x), f2tf(v.y), f2tf(v.z), f2tf(v.w));
            *(uint4*)&As[row][c4 * 4] = u;
        }
#pragma unroll
        for (int i = 0; i < 2; i++) {
            int f4 = tid + i * 256;
            int kr = f4 >> 4;
            int c4 = f4 & 15;
            float4 v = *(const float4*)(W + (size_t)(k0 + kr) * DMODEL + c0 + c4 * 4);
            Bs[c4 * 4 + 0][kr] = f2tf(v.x);
            Bs[c4 * 4 + 1][kr] = f2tf(v.y);
            Bs[c4 * 4 + 2][kr] = f2tf(v.z);
            Bs[c4 * 4 + 3][kr] = f2tf(v.w);
        }
        __syncthreads();

#pragma unroll
        for (int ks = 0; ks < 4; ks++) {
            const int kk = ks * 8;
            unsigned af[2][4], bf[4][2];
#pragma unroll
            for (int mt = 0; mt < 2; mt++) {
                int r = wm * 32 + mt * 16;
                af[mt][0] = As[r + g][kk + t];
                af[mt][1] = As[r + g + 8][kk + t];
                af[mt][2] = As[r + g][kk + t + 4];
                af[mt][3] = As[r + g + 8][kk + t + 4];
            }
#pragma unroll
            for (int nt = 0; nt < 4; nt++) {
                int n = wn * 32 + nt * 8;
                bf[nt][0] = Bs[n + g][kk + t];
                bf[nt][1] = Bs[n + g][kk + t + 4];
            }
#pragma unroll
            for (int mt = 0; mt < 2; mt++)
#pragma unroll
                for (int nt = 0; nt < 4; nt++)
                    mma_tf32(acc[mt][nt], af[mt], bf[nt]);
        }
    }

#pragma unroll
    for (int mt = 0; mt < 2; mt++)
#pragma unroll
        for (int nt = 0; nt < 4; nt++)
#pragma unroll
            for (int half = 0; half < 2; half++) {
                int m = m0 + wm * 32 + mt * 16 + g + half * 8;
                int c = c0 + wn * 32 + nt * 8 + 2 * t;
                *(float2*)&Cext[(size_t)m * DMODEL + c] =
                    make_float2(acc[mt][nt][half * 2 + 0], acc[mt][nt][half * 2 + 1]);
            }
}

// ---------------------------------------------------------------------------
// Flash attention: cp.async double-buffered staging of pre-laid-out K/V.
// Block = 128 query rows (8 warps x 16), key chunks of 64.
// dynamic smem: Ks[2][64][68] + Vt[2][64][68] = 69632 B
// ---------------------------------------------------------------------------
#define CHUNK_WORDS (64 * 68)          // 4352 words per tile buffer

__global__ __launch_bounds__(256)
void attn_tf32(const float* __restrict__ bias)
{
    extern __shared__ unsigned smem_u[];
    unsigned* Ksm = smem_u;                     // [2][64][68]
    unsigned* Vsm = smem_u + 2 * CHUNK_WORDS;   // [2][64][68]

    const int tid  = threadIdx.x;
    const int warp = tid >> 5, lane = tid & 31;
    const int g = lane >> 2, t = lane & 3;
    const int bh = blockIdx.y;
    const int h  = bh & (HEADS - 1);
    const int b  = bh >> 3;
    const int qw = blockIdx.x * 128 + warp * 16;

    const float* __restrict__ Qg = g_q + (size_t)bh * SEQ * DIM_HEAD;
    const float* __restrict__ Kg = g_k + (size_t)bh * SEQ * DIM_HEAD;
    const float* __restrict__ Vg = g_v + (size_t)bh * DIM_HEAD * SEQ;
    const float* __restrict__ bp0 = bias + ((size_t)h * SEQ + qw + g) * SEQ;
    const float* __restrict__ bp1 = bias + ((size_t)h * SEQ + qw + g + 8) * SEQ;

    const unsigned ks_base = (unsigned)__cvta_generic_to_shared(Ksm);
    const unsigned vs_base = (unsigned)__cvta_generic_to_shared(Vsm);

    // Q A-frags (g_q pre-scaled + pre-rounded)
    unsigned qa[8][4];
#pragma unroll
    for (int s = 0; s < 8; s++) {
        qa[s][0] = __float_as_uint(Qg[(size_t)(qw + g)     * DIM_HEAD + 8 * s + t]);
        qa[s][1] = __float_as_uint(Qg[(size_t)(qw + g + 8) * DIM_HEAD + 8 * s + t]);
        qa[s][2] = __float_as_uint(Qg[(size_t)(qw + g)     * DIM_HEAD + 8 * s + t + 4]);
        qa[s][3] = __float_as_uint(Qg[(size_t)(qw + g + 8) * DIM_HEAD + 8 * s + t + 4]);
    }

    float o[8][4];
#pragma unroll
    for (int i = 0; i < 8; i++)
#pragma unroll
        for (int j = 0; j < 4; j++) o[i][j] = 0.f;

    float m0r = -1e30f, m1r = -1e30f, l0 = 0.f, l1 = 0.f;

    const int crow = tid >> 4;       // 0..15 -> handles rows crow, +16, +32, +48
    const int cq   = tid & 15;       // 16B granule within 64-word row

    // issue cp.async for chunk at key offset kt into buffer buf
#define ISSUE_CHUNK(kt, buf)                                                          \
    {                                                                                 \
        _Pragma("unroll")                                                             \
        for (int i = 0; i < 4; i++) {                                                 \
            int row = crow + i * 16;                                                  \
            unsigned off = ((buf) * CHUNK_WORDS + row * 68 + cq * 4) * 4;             \
            const float* ksrc = Kg + (size_t)((kt) + row) * DIM_HEAD + cq * 4;        \
            asm volatile("cp.async.cg.shared.global [%0], [%1], 16;\n"                \
                         :: "r"(ks_base + off), "l"(ksrc));                           \
            const float* vsrc = Vg + (size_t)row * SEQ + (kt) + cq * 4;               \
            asm volatile("cp.async.cg.shared.global [%0], [%1], 16;\n"                \
                         :: "r"(vs_base + off), "l"(vsrc));                           \
        }                                                                             \
        asm volatile("cp.async.commit_group;\n");                                     \
    }

    ISSUE_CHUNK(0, 0);

    for (int c = 0; c < SEQ / 64; c++) {
        const int buf = c & 1;
        const int kt = c * 64;
        if (c + 1 < SEQ / 64) {
            __syncthreads();                    // buf^1 no longer being read
            ISSUE_CHUNK(kt + 64, buf ^ 1);
            asm volatile("cp.async.wait_group 1;\n");
        } else {
            asm volatile("cp.async.wait_group 0;\n");
        }
        __syncthreads();

        const unsigned* Ks = Ksm + buf * CHUNK_WORDS;
        const unsigned* Vt = Vsm + buf * CHUNK_WORDS;

        // S = Q K^T
        float s[8][4];
#pragma unroll
        for (int i = 0; i < 8; i++)
#pragma unroll
            for (int j = 0; j < 4; j++) s[i][j] = 0.f;

#pragma unroll
        for (int ntp = 0; ntp < 4; ntp++) {
            Frag8 f0, f1;
            load_frag8(Ks + (ntp * 16 + g) * 68,     t, f0);
            load_frag8(Ks + (ntp * 16 + 8 + g) * 68, t, f1);
#pragma unroll
            for (int ks = 0; ks < 8; ks++) {
                unsigned bf0[2] = {f0.a[ks], f0.b[ks]};
                mma_tf32(s[2 * ntp], qa[ks], bf0);
                unsigned bf1[2] = {f1.a[ks], f1.b[ks]};
                mma_tf32(s[2 * ntp + 1], qa[ks], bf1);
            }
        }

        // bias + running max
        float mx0 = m0r, mx1 = m1r;
#pragma unroll
        for (int nt = 0; nt < 8; nt++) {
            float2 bb0 = *(const float2*)(bp0 + kt + nt * 8 + 2 * t);
            float2 bb1 = *(const float2*)(bp1 + kt + nt * 8 + 2 * t);
            s[nt][0] += bb0.x; s[nt][1] += bb0.y;
            s[nt][2] += bb1.x; s[nt][3] += bb1.y;
            mx0 = fmaxf(mx0, fmaxf(s[nt][0], s[nt][1]));
            mx1 = fmaxf(mx1, fmaxf(s[nt][2], s[nt][3]));
        }
        mx0 = fmaxf(mx0, __shfl_xor_sync(FULLMASK, mx0, 1));
        mx0 = fmaxf(mx0, __shfl_xor_sync(FULLMASK, mx0, 2));
        mx1 = fmaxf(mx1, __shfl_xor_sync(FULLMASK, mx1, 1));
        mx1 = fmaxf(mx1, __shfl_xor_sync(FULLMASK, mx1, 2));

        const float cr0 = __expf(m0r - mx0);
        const float cr1 = __expf(m1r - mx1);
        m0r = mx0; m1r = mx1;

        float ls0 = 0.f, ls1 = 0.f;
#pragma unroll
        for (int nt = 0; nt < 8; nt++) {
            s[nt][0] = __expf(s[nt][0] - mx0);
            s[nt][1] = __expf(s[nt][1] - mx0);
            s[nt][2] = __expf(s[nt][2] - mx1);
            s[nt][3] = __expf(s[nt][3] - mx1);
            ls0 += s[nt][0] + s[nt][1];
            ls1 += s[nt][2] + s[nt][3];
            o[nt][0] *= cr0; o[nt][1] *= cr0;
            o[nt][2] *= cr1; o[nt][3] *= cr1;
        }
        ls0 += __shfl_xor_sync(FULLMASK, ls0, 1);
        ls0 += __shfl_xor_sync(FULLMASK, ls0, 2);
        ls1 += __shfl_xor_sync(FULLMASK, ls1, 1);
        ls1 += __shfl_xor_sync(FULLMASK, ls1, 2);
        l0 = l0 * cr0 + ls0;
        l1 = l1 * cr1 + ls1;

        // relayout P: C-frag -> A-frag via quad shuffles
        unsigned pa_[8][4];
        const int l0q = (lane & ~3) | (t >> 1);
        const int l1q = (lane & ~3) | (2 + (t >> 1));
        const bool odd = t & 1;
#pragma unroll
        for (int j = 0; j < 8; j++) {
            float v00 = __shfl_sync(FULLMASK, s[j][0], l0q);
            float v01 = __shfl_sync(FULLMASK, s[j][1], l0q);
            float v02 = __shfl_sync(FULLMASK, s[j][2], l0q);
            float v03 = __shfl_sync(FULLMASK, s[j][3], l0q);
            float v10 = __shfl_sync(FULLMASK, s[j][0], l1q);
            float v11 = __shfl_sync(FULLMASK, s[j][1], l1q);
            float v12 = __shfl_sync(FULLMASK, s[j][2], l1q);
            float v13 = __shfl_sync(FULLMASK, s[j][3], l1q);
            pa_[j][0] = f2tf(odd ? v01 : v00);
            pa_[j][1] = f2tf(odd ? v03 : v02);
            pa_[j][2] = f2tf(odd ? v11 : v10);
            pa_[j][3] = f2tf(odd ? v13 : v12);
        }

        // O += P @ V
#pragma unroll
        for (int ntp = 0; ntp < 4; ntp++) {
            Frag8 f0, f1;
            load_frag8(Vt + (ntp * 16 + g) * 68,     t, f0);
            load_frag8(Vt + (ntp * 16 + 8 + g) * 68, t, f1);
#pragma unroll
            for (int j = 0; j < 8; j++) {
                unsigned bf0[2] = {f0.a[j], f0.b[j]};
                mma_tf32(o[2 * ntp], pa_[j], bf0);
                unsigned bf1[2] = {f1.a[j], f1.b[j]};
                mma_tf32(o[2 * ntp + 1], pa_[j], bf1);
            }
        }
    }

    // normalize + write g_o
    const float inv0 = 1.f / l0, inv1 = 1.f / l1;
    float* __restrict__ Og = g_o + ((size_t)b * SEQ + qw) * DMODEL + h * DIM_HEAD;
#pragma unroll
    for (int nt = 0; nt < 8; nt++) {
        *(float2*)&Og[(size_t)g * DMODEL + nt * 8 + 2 * t] =
            make_float2(o[nt][0] * inv0, o[nt][1] * inv0);
        *(float2*)&Og[(size_t)(g + 8) * DMODEL + nt * 8 + 2 * t] =
            make_float2(o[nt][2] * inv1, o[nt][3] * inv1);
    }
}

// ---------------------------------------------------------------------------
extern "C" void kernel_launch(void* const* d_in, const int* in_sizes, int n_in,
                              void* d_out, int out_size)
{
    const float* query = (const float*)d_in[0];
    const float* bias  = (const float*)d_in[1];
    const float* Wq    = (const float*)d_in[2];
    const float* Wk    = (const float*)d_in[3];
    const float* Wv    = (const float*)d_in[4];
    const float* Wout  = (const float*)d_in[5];
    float* out = (float*)d_out;

    const int attn_smem = 4 * CHUNK_WORDS * 4;   // 69632 B
    cudaFuncSetAttribute(attn_tf32, cudaFuncAttributeMaxDynamicSharedMemorySize,
                         attn_smem);

    dim3 qkv_grid(DMODEL / 64, M_ROWS / 128, 3);   // (8, 64, 3)
    gemm_qkv<<<qkv_grid, 256>>>(query, Wq, Wk, Wv);

    dim3 attn_grid(SEQ / 128, BATCH * HEADS);      // (16, 32)
    attn_tf32<<<attn_grid, 256, attn_smem>>>(bias);

    dim3 out_grid(DMODEL / 64, M_ROWS / 128);      // (8, 64)
    gemm_out<<<out_grid, 256>>>(Wout, out);
}

// round 8
// speedup vs baseline: 2.9473x; 1.0007x over previous
#include <cuda_runtime.h>

#define HEADS 8
#define DIM_HEAD 64
#define BATCH 4
#define SEQ 2048
#define DMODEL 512
#define M_ROWS (BATCH * SEQ)           // 8192
#define QK_SCALE 0.125f                // 64^-0.5
#define FULLMASK 0xffffffffu
#define PERM(c) ((((c) & 7) << 3) | ((c) >> 3))   // k-contiguous fragment perm (64-wide)

// Scratch (device-global; no allocation allowed)
// g_a:  [m][ (k&~63)+PERM(k&63) ]  query, tf32-rounded
// g_wt: [z][n][ (k&~63)+PERM(k&63) ] transposed weights, tf32-rounded (z: q,k,v,out)
// g_q:  [b,h,n,d]       pre-scaled by QK_SCALE, tf32-rounded
// g_k:  [b,h,n,PERM(d)] tf32-rounded
// g_v:  [b,h,d,(n&~63)+PERM(n&63)] tf32-rounded, transposed
// g_o:  [b,n][ (c&~63)+PERM(c&63) ] attn out, tf32-rounded (c = h*64+d)
__device__ float g_a[M_ROWS * DMODEL];
__device__ float g_wt[4 * DMODEL * DMODEL];
__device__ float g_q[BATCH * HEADS * SEQ * DIM_HEAD];
__device__ float g_k[BATCH * HEADS * SEQ * DIM_HEAD];
__device__ float g_v[BATCH * HEADS * SEQ * DIM_HEAD];
__device__ float g_o[BATCH * SEQ * DMODEL];

__device__ __forceinline__ unsigned f2tf(float x) {
    unsigned u;
    asm("cvt.rna.tf32.f32 %0, %1;" : "=r"(u) : "f"(x));
    return u;
}
__device__ __forceinline__ float roundtf(float x) { return __uint_as_float(f2tf(x)); }

__device__ __forceinline__ void mma_tf32(float* c, const unsigned* a, const unsigned* b) {
    asm volatile(
        "mma.sync.aligned.m16n8k8.row.col.f32.tf32.tf32.f32 "
        "{%0,%1,%2,%3}, {%4,%5,%6,%7}, {%8,%9}, {%0,%1,%2,%3};"
        : "+f"(c[0]), "+f"(c[1]), "+f"(c[2]), "+f"(c[3])
        : "r"(a[0]), "r"(a[1]), "r"(a[2]), "r"(a[3]), "r"(b[0]), "r"(b[1]));
}

// Load one smem row's fragment words for all 8 k-steps: 4x LDS.128.
struct Frag8 { unsigned a[8]; unsigned b[8]; };
__device__ __forceinline__ void load_frag8(const unsigned* base, int t, Frag8& f) {
    const uint4* p = (const uint4*)base;
    uint4 x0 = p[t * 2], x1 = p[t * 2 + 1];
    uint4 y0 = p[(t + 4) * 2], y1 = p[(t + 4) * 2 + 1];
    f.a[0] = x0.x; f.a[1] = x0.y; f.a[2] = x0.z; f.a[3] = x0.w;
    f.a[4] = x1.x; f.a[5] = x1.y; f.a[6] = x1.z; f.a[7] = x1.w;
    f.b[0] = y0.x; f.b[1] = y0.y; f.b[2] = y0.z; f.b[3] = y0.w;
    f.b[4] = y1.x; f.b[5] = y1.y; f.b[6] = y1.z; f.b[7] = y1.w;
}

// ---------------------------------------------------------------------------
// prep_a: query -> g_a (tf32-rounded, PERM within each 64-wide k block)
// ---------------------------------------------------------------------------
__global__ __launch_bounds__(256)
void prep_a(const float* __restrict__ query)
{
    int idx = blockIdx.x * 256 + threadIdx.x;      // over 8192*128 float4s
    int m = idx >> 7, c4 = idx & 127;
    int k = c4 * 4;
    float4 v = *(const float4*)(query + (size_t)m * DMODEL + k);
    float* dst = g_a + (size_t)m * DMODEL + (k & ~63);
    dst[PERM((k + 0) & 63)] = roundtf(v.x);
    dst[PERM((k + 1) & 63)] = roundtf(v.y);
    dst[PERM((k + 2) & 63)] = roundtf(v.z);
    dst[PERM((k + 3) & 63)] = roundtf(v.w);
}

// ---------------------------------------------------------------------------
// prep_w: W[k][n] -> g_wt[z][n][(k&~63)+PERM(k&63)] tf32-rounded (smem tile)
// grid (n0/64=8, k0/64=8, 4)
// ---------------------------------------------------------------------------
__global__ __launch_bounds__(256)
void prep_w(const float* __restrict__ W0, const float* __restrict__ W1,
            const float* __restrict__ W2, const float* __restrict__ W3)
{
    __shared__ float sm[64][68];
    const int z = blockIdx.z;
    const float* __restrict__ W = (z == 0) ? W0 : (z == 1) ? W1 : (z == 2) ? W2 : W3;
    const int n0 = blockIdx.x * 64;
    const int k0 = blockIdx.y * 64;
    const int tid = threadIdx.x;

#pragma unroll
    for (int i = 0; i < 4; i++) {
        int f4 = tid + i * 256;
        int kr = f4 >> 4, nq = f4 & 15;
        float4 v = *(const float4*)(W + (size_t)(k0 + kr) * DMODEL + n0 + nq * 4);
        sm[nq * 4 + 0][PERM(kr)] = roundtf(v.x);
        sm[nq * 4 + 1][PERM(kr)] = roundtf(v.y);
        sm[nq * 4 + 2][PERM(kr)] = roundtf(v.z);
        sm[nq * 4 + 3][PERM(kr)] = roundtf(v.w);
    }
    __syncthreads();
    float* dstz = g_wt + (size_t)z * DMODEL * DMODEL;
#pragma unroll
    for (int i = 0; i < 4; i++) {
        int f4 = tid + i * 256;
        int nr = f4 >> 4, q = f4 & 15;
        *(float4*)(dstz + (size_t)(n0 + nr) * DMODEL + k0 + q * 4) =
            *(const float4*)&sm[nr][q * 4];
    }
}

// ---------------------------------------------------------------------------
// Fast tf32 GEMM: C[8192,512] = A @ W, operands pre-rounded + pre-permuted.
// block 256 = 8 warps (4M x 2N), tile 128x64, K-block 64, cp.async dbl-buffer.
// OUT=false: A=g_a, B=g_wt[z], epilogue -> g_q/g_k/g_v layouts
// OUT=true : A=g_o, B=g_wt[3], epilogue -> external out
// dynamic smem: As[2][128][68] + Bs[2][64][68] = 104448 B
// ---------------------------------------------------------------------------
#define GA_WORDS (128 * 68)
#define GB_WORDS (64 * 68)

template <bool OUT>
__global__ __launch_bounds__(256)
void gemm_fast(float* __restrict__ Cext)
{
    extern __shared__ unsigned gsm[];
    unsigned* Asm = gsm;                    // [2][128][68]
    unsigned* Bsm = gsm + 2 * GA_WORDS;     // [2][64][68]

    const int z = OUT ? 3 : blockIdx.z;
    const float* __restrict__ A = OUT ? g_o : g_a;
    const float* __restrict__ B = g_wt + (size_t)z * DMODEL * DMODEL;

    const int tid  = threadIdx.x;
    const int warp = tid >> 5, lane = tid & 31;
    const int g = lane >> 2, t = lane & 3;
    const int wm = warp & 3, wn = warp >> 2;
    const int m0 = blockIdx.y * 128;
    const int c0 = blockIdx.x * 64;

    const unsigned as_base = (unsigned)__cvta_generic_to_shared(Asm);
    const unsigned bs_base = (unsigned)__cvta_generic_to_shared(Bsm);

    float acc[2][4][4];
#pragma unroll
    for (int i = 0; i < 2; i++)
#pragma unroll
        for (int j = 0; j < 4; j++)
#pragma unroll
            for (int k = 0; k < 4; k++) acc[i][j][k] = 0.f;

    // A tile: 128 rows x 16 chunks(16B) = 2048 -> 8/thread
    // B tile:  64 rows x 16 chunks      = 1024 -> 4/thread
#define G_ISSUE(k0, buf)                                                              \
    {                                                                                 \
        _Pragma("unroll")                                                             \
        for (int i = 0; i < 8; i++) {                                                 \
            int f4  = tid + i * 256;                                                  \
            int row = f4 >> 4, q = f4 & 15;                                           \
            const float* src = A + (size_t)(m0 + row) * DMODEL + (k0) + q * 4;        \
            unsigned dst = as_base + ((buf) * GA_WORDS + row * 68 + q * 4) * 4;       \
            asm volatile("cp.async.cg.shared.global [%0], [%1], 16;\n"                \
                         :: "r"(dst), "l"(src));                                      \
        }                                                                             \
        _Pragma("unroll")                                                             \
        for (int i = 0; i < 4; i++) {                                                 \
            int f4  = tid + i * 256;                                                  \
            int row = f4 >> 4, q = f4 & 15;                                           \
            const float* src = B + (size_t)(c0 + row) * DMODEL + (k0) + q * 4;        \
            unsigned dst = bs_base + ((buf) * GB_WORDS + row * 68 + q * 4) * 4;       \
            asm volatile("cp.async.cg.shared.global [%0], [%1], 16;\n"                \
                         :: "r"(dst), "l"(src));                                      \
        }                                                                             \
        asm volatile("cp.async.commit_group;\n");                                     \
    }

    G_ISSUE(0, 0);

    for (int c = 0; c < DMODEL / 64; c++) {
        const int buf = c & 1;
        if (c + 1 < DMODEL / 64) {
            __syncthreads();
            G_ISSUE((c + 1) * 64, buf ^ 1);
            asm volatile("cp.async.wait_group 1;\n");
        } else {
            asm volatile("cp.async.wait_group 0;\n");
        }
        __syncthreads();

        const unsigned* Asb = Asm + buf * GA_WORDS;
        const unsigned* Bsb = Bsm + buf * GB_WORDS;

        Frag8 fa[4];
        load_frag8(Asb + (wm * 32 + g) * 68,      t, fa[0]);
        load_frag8(Asb + (wm * 32 + 8 + g) * 68,  t, fa[1]);
        load_frag8(Asb + (wm * 32 + 16 + g) * 68, t, fa[2]);
        load_frag8(Asb + (wm * 32 + 24 + g) * 68, t, fa[3]);

#pragma unroll
        for (int nt = 0; nt < 4; nt++) {
            Frag8 fb;
            load_frag8(Bsb + (wn * 32 + nt * 8 + g) * 68, t, fb);
#pragma unroll
            for (int ks = 0; ks < 8; ks++) {
                unsigned bfr[2] = {fb.a[ks], fb.b[ks]};
                unsigned af0[4] = {fa[0].a[ks], fa[1].a[ks], fa[0].b[ks], fa[1].b[ks]};
                mma_tf32(acc[0][nt], af0, bfr);
                unsigned af1[4] = {fa[2].a[ks], fa[3].a[ks], fa[2].b[ks], fa[3].b[ks]};
                mma_tf32(acc[1][nt], af1, bfr);
            }
        }
    }
#undef G_ISSUE

    // epilogue
#pragma unroll
    for (int mt = 0; mt < 2; mt++) {
#pragma unroll
        for (int nt = 0; nt < 4; nt++) {
#pragma unroll
            for (int half = 0; half < 2; half++) {
                int m = m0 + wm * 32 + mt * 16 + g + half * 8;
                int c = c0 + wn * 32 + nt * 8 + 2 * t;
                float v0 = acc[mt][nt][half * 2 + 0];
                float v1 = acc[mt][nt][half * 2 + 1];
                if (OUT) {
                    *(float2*)&Cext[(size_t)m * DMODEL + c] = make_float2(v0, v1);
                } else {
                    int b = m >> 11, n = m & 2047;
                    int hh = c >> 6, d = c & 63;
                    size_t bh = (size_t)b * HEADS + hh;
                    if (z == 0) {
                        *(float2*)&g_q[(bh * SEQ + n) * DIM_HEAD + d] =
                            make_float2(roundtf(v0 * QK_SCALE), roundtf(v1 * QK_SCALE));
                    } else if (z == 1) {
                        float* dst = &g_k[(bh * SEQ + n) * DIM_HEAD];
                        dst[PERM(d)]     = roundtf(v0);
                        dst[PERM(d + 1)] = roundtf(v1);
                    } else {
                        int np = (n & ~63) + PERM(n & 63);
                        g_v[(bh * DIM_HEAD + d) * SEQ + np]     = roundtf(v0);
                        g_v[(bh * DIM_HEAD + d + 1) * SEQ + np] = roundtf(v1);
                    }
                }
            }
        }
    }
}

// ---------------------------------------------------------------------------
// Flash attention: cp.async double-buffered staging of pre-laid-out K/V.
// Block = 128 query rows (8 warps x 16), key chunks of 64.
// dynamic smem: Ks[2][64][68] + Vt[2][64][68] = 69632 B
// ---------------------------------------------------------------------------
#define CHUNK_WORDS (64 * 68)

__global__ __launch_bounds__(256)
void attn_tf32(const float* __restrict__ bias)
{
    extern __shared__ unsigned smem_u[];
    unsigned* Ksm = smem_u;
    unsigned* Vsm = smem_u + 2 * CHUNK_WORDS;

    const int tid  = threadIdx.x;
    const int warp = tid >> 5, lane = tid & 31;
    const int g = lane >> 2, t = lane & 3;
    const int bh = blockIdx.y;
    const int h  = bh & (HEADS - 1);
    const int b  = bh >> 3;
    const int qw = blockIdx.x * 128 + warp * 16;

    const float* __restrict__ Qg = g_q + (size_t)bh * SEQ * DIM_HEAD;
    const float* __restrict__ Kg = g_k + (size_t)bh * SEQ * DIM_HEAD;
    const float* __restrict__ Vg = g_v + (size_t)bh * DIM_HEAD * SEQ;
    const float* __restrict__ bp0 = bias + ((size_t)h * SEQ + qw + g) * SEQ;
    const float* __restrict__ bp1 = bias + ((size_t)h * SEQ + qw + g + 8) * SEQ;

    const unsigned ks_base = (unsigned)__cvta_generic_to_shared(Ksm);
    const unsigned vs_base = (unsigned)__cvta_generic_to_shared(Vsm);

    unsigned qa[8][4];
#pragma unroll
    for (int s = 0; s < 8; s++) {
        qa[s][0] = __float_as_uint(Qg[(size_t)(qw + g)     * DIM_HEAD + 8 * s + t]);
        qa[s][1] = __float_as_uint(Qg[(size_t)(qw + g + 8) * DIM_HEAD + 8 * s + t]);
        qa[s][2] = __float_as_uint(Qg[(size_t)(qw + g)     * DIM_HEAD + 8 * s + t + 4]);
        qa[s][3] = __float_as_uint(Qg[(size_t)(qw + g + 8) * DIM_HEAD + 8 * s + t + 4]);
    }

    float o[8][4];
#pragma unroll
    for (int i = 0; i < 8; i++)
#pragma unroll
        for (int j = 0; j < 4; j++) o[i][j] = 0.f;

    float m0r = -1e30f, m1r = -1e30f, l0 = 0.f, l1 = 0.f;

    const int crow = tid >> 4;
    const int cq   = tid & 15;

#define ISSUE_CHUNK(kt, buf)                                                          \
    {                                                                                 \
        _Pragma("unroll")                                                             \
        for (int i = 0; i < 4; i++) {                                                 \
            int row = crow + i * 16;                                                  \
            unsigned off = ((buf) * CHUNK_WORDS + row * 68 + cq * 4) * 4;             \
            const float* ksrc = Kg + (size_t)((kt) + row) * DIM_HEAD + cq * 4;        \
            asm volatile("cp.async.cg.shared.global [%0], [%1], 16;\n"                \
                         :: "r"(ks_base + off), "l"(ksrc));                           \
            const float* vsrc = Vg + (size_t)row * SEQ + (kt) + cq * 4;               \
            asm volatile("cp.async.cg.shared.global [%0], [%1], 16;\n"                \
                         :: "r"(vs_base + off), "l"(vsrc));                           \
        }                                                                             \
        asm volatile("cp.async.commit_group;\n");                                     \
    }

    ISSUE_CHUNK(0, 0);

    for (int c = 0; c < SEQ / 64; c++) {
        const int buf = c & 1;
        const int kt = c * 64;
        if (c + 1 < SEQ / 64) {
            __syncthreads();
            ISSUE_CHUNK(kt + 64, buf ^ 1);
            asm volatile("cp.async.wait_group 1;\n");
        } else {
            asm volatile("cp.async.wait_group 0;\n");
        }
        __syncthreads();

        const unsigned* Ks = Ksm + buf * CHUNK_WORDS;
        const unsigned* Vt = Vsm + buf * CHUNK_WORDS;

        float s[8][4];
#pragma unroll
        for (int i = 0; i < 8; i++)
#pragma unroll
            for (int j = 0; j < 4; j++) s[i][j] = 0.f;

#pragma unroll
        for (int ntp = 0; ntp < 4; ntp++) {
            Frag8 f0, f1;
            load_frag8(Ks + (ntp * 16 + g) * 68,     t, f0);
            load_frag8(Ks + (ntp * 16 + 8 + g) * 68, t, f1);
#pragma unroll
            for (int ks = 0; ks < 8; ks++) {
                unsigned bf0[2] = {f0.a[ks], f0.b[ks]};
                mma_tf32(s[2 * ntp], qa[ks], bf0);
                unsigned bf1[2] = {f1.a[ks], f1.b[ks]};
                mma_tf32(s[2 * ntp + 1], qa[ks], bf1);
            }
        }

        float mx0 = m0r, mx1 = m1r;
#pragma unroll
        for (int nt = 0; nt < 8; nt++) {
            float2 bb0 = *(const float2*)(bp0 + kt + nt * 8 + 2 * t);
            float2 bb1 = *(const float2*)(bp1 + kt + nt * 8 + 2 * t);
            s[nt][0] += bb0.x; s[nt][1] += bb0.y;
            s[nt][2] += bb1.x; s[nt][3] += bb1.y;
            mx0 = fmaxf(mx0, fmaxf(s[nt][0], s[nt][1]));
            mx1 = fmaxf(mx1, fmaxf(s[nt][2], s[nt][3]));
        }
        mx0 = fmaxf(mx0, __shfl_xor_sync(FULLMASK, mx0, 1));
        mx0 = fmaxf(mx0, __shfl_xor_sync(FULLMASK, mx0, 2));
        mx1 = fmaxf(mx1, __shfl_xor_sync(FULLMASK, mx1, 1));
        mx1 = fmaxf(mx1, __shfl_xor_sync(FULLMASK, mx1, 2));

        const float cr0 = __expf(m0r - mx0);
        const float cr1 = __expf(m1r - mx1);
        m0r = mx0; m1r = mx1;

        float ls0 = 0.f, ls1 = 0.f;
#pragma unroll
        for (int nt = 0; nt < 8; nt++) {
            s[nt][0] = __expf(s[nt][0] - mx0);
            s[nt][1] = __expf(s[nt][1] - mx0);
            s[nt][2] = __expf(s[nt][2] - mx1);
            s[nt][3] = __expf(s[nt][3] - mx1);
            ls0 += s[nt][0] + s[nt][1];
            ls1 += s[nt][2] + s[nt][3];
            o[nt][0] *= cr0; o[nt][1] *= cr0;
            o[nt][2] *= cr1; o[nt][3] *= cr1;
        }
        ls0 += __shfl_xor_sync(FULLMASK, ls0, 1);
        ls0 += __shfl_xor_sync(FULLMASK, ls0, 2);
        ls1 += __shfl_xor_sync(FULLMASK, ls1, 1);
        ls1 += __shfl_xor_sync(FULLMASK, ls1, 2);
        l0 = l0 * cr0 + ls0;
        l1 = l1 * cr1 + ls1;

        unsigned pa_[8][4];
        const int l0q = (lane & ~3) | (t >> 1);
        const int l1q = (lane & ~3) | (2 + (t >> 1));
        const bool odd = t & 1;
#pragma unroll
        for (int j = 0; j < 8; j++) {
            float v00 = __shfl_sync(FULLMASK, s[j][0], l0q);
            float v01 = __shfl_sync(FULLMASK, s[j][1], l0q);
            float v02 = __shfl_sync(FULLMASK, s[j][2], l0q);
            float v03 = __shfl_sync(FULLMASK, s[j][3], l0q);
            float v10 = __shfl_sync(FULLMASK, s[j][0], l1q);
            float v11 = __shfl_sync(FULLMASK, s[j][1], l1q);
            float v12 = __shfl_sync(FULLMASK, s[j][2], l1q);
            float v13 = __shfl_sync(FULLMASK, s[j][3], l1q);
            pa_[j][0] = f2tf(odd ? v01 : v00);
            pa_[j][1] = f2tf(odd ? v03 : v02);
            pa_[j][2] = f2tf(odd ? v11 : v10);
            pa_[j][3] = f2tf(odd ? v13 : v12);
        }

#pragma unroll
        for (int ntp = 0; ntp < 4; ntp++) {
            Frag8 f0, f1;
            load_frag8(Vt + (ntp * 16 + g) * 68,     t, f0);
            load_frag8(Vt + (ntp * 16 + 8 + g) * 68, t, f1);
#pragma unroll
            for (int j = 0; j < 8; j++) {
                unsigned bf0[2] = {f0.a[j], f0.b[j]};
                mma_tf32(o[2 * ntp], pa_[j], bf0);
                unsigned bf1[2] = {f1.a[j], f1.b[j]};
                mma_tf32(o[2 * ntp + 1], pa_[j], bf1);
            }
        }
    }

    // normalize + write g_o (tf32-rounded, PERM'd for gemm_fast<OUT> A-path)
    const float inv0 = 1.f / l0, inv1 = 1.f / l1;
    float* __restrict__ Og = g_o + ((size_t)b * SEQ + qw) * DMODEL + h * DIM_HEAD;
#pragma unroll
    for (int nt = 0; nt < 8; nt++) {
        int cc = nt * 8 + 2 * t;            // even
        int p = PERM(cc);                   // PERM(cc+1) == p + 8
        Og[(size_t)g * DMODEL + p]           = roundtf(o[nt][0] * inv0);
        Og[(size_t)g * DMODEL + p + 8]       = roundtf(o[nt][1] * inv0);
        Og[(size_t)(g + 8) * DMODEL + p]     = roundtf(o[nt][2] * inv1);
        Og[(size_t)(g + 8) * DMODEL + p + 8] = roundtf(o[nt][3] * inv1);
    }
}

// ---------------------------------------------------------------------------
extern "C" void kernel_launch(void* const* d_in, const int* in_sizes, int n_in,
                              void* d_out, int out_size)
{
    const float* query = (const float*)d_in[0];
    const float* bias  = (const float*)d_in[1];
    const float* Wq    = (const float*)d_in[2];
    const float* Wk    = (const float*)d_in[3];
    const float* Wv    = (const float*)d_in[4];
    const float* Wout  = (const float*)d_in[5];
    float* out = (float*)d_out;

    const int attn_smem = 4 * CHUNK_WORDS * 4;           // 69632 B
    const int gemm_smem = 2 * (GA_WORDS + GB_WORDS) * 4; // 104448 B
    cudaFuncSetAttribute(attn_tf32, cudaFuncAttributeMaxDynamicSharedMemorySize,
                         attn_smem);
    cudaFuncSetAttribute(gemm_fast<false>, cudaFuncAttributeMaxDynamicSharedMemorySize,
                         gemm_smem);
    cudaFuncSetAttribute(gemm_fast<true>, cudaFuncAttributeMaxDynamicSharedMemorySize,
                         gemm_smem);

    prep_a<<<M_ROWS * (DMODEL / 4) / 256, 256>>>(query);
    prep_w<<<dim3(8, 8, 4), 256>>>(Wq, Wk, Wv, Wout);

    dim3 qkv_grid(DMODEL / 64, M_ROWS / 128, 3);   // (8, 64, 3)
    gemm_fast<false><<<qkv_grid, 256, gemm_smem>>>(nullptr);

    dim3 attn_grid(SEQ / 128, BATCH * HEADS);      // (16, 32)
    attn_tf32<<<attn_grid, 256, attn_smem>>>(bias);

    dim3 out_grid(DMODEL / 64, M_ROWS / 128);      // (8, 64)
    gemm_fast<true><<<out_grid, 256, gemm_smem>>>(out);
}

// round 11
// speedup vs baseline: 3.6942x; 1.2534x over previous
#include <cuda_runtime.h>

#define HEADS 8
#define DIM_HEAD 64
#define BATCH 4
#define SEQ 2048
#define DMODEL 512
#define M_ROWS (BATCH * SEQ)           // 8192
#define QK_SCALE 0.125f                // 64^-0.5
#define FULLMASK 0xffffffffu
#define PERM(c) ((((c) & 7) << 3) | ((c) >> 3))   // k-contiguous fragment perm (64-wide)

// Scratch (device-global; no allocation allowed)
// g_a:  [m][ (k&~63)+PERM(k&63) ]  query, tf32-rounded
// g_wt: [z][n][ (k&~63)+PERM(k&63) ] transposed weights, tf32-rounded (z: q,k,v,out)
// g_q:  [b,h,n,d]       pre-scaled by QK_SCALE, tf32-rounded
// g_k:  [b,h,n,PERM(d)] tf32-rounded
// g_v:  [b,h,d,(n&~63)+PERM(n&63)] tf32-rounded, transposed
// g_o:  [b,n][ (c&~63)+PERM(c&63) ] attn out, tf32-rounded (c = h*64+d)
__device__ float g_a[M_ROWS * DMODEL];
__device__ float g_wt[4 * DMODEL * DMODEL];
__device__ float g_q[BATCH * HEADS * SEQ * DIM_HEAD];
__device__ float g_k[BATCH * HEADS * SEQ * DIM_HEAD];
__device__ float g_v[BATCH * HEADS * SEQ * DIM_HEAD];
__device__ float g_o[BATCH * SEQ * DMODEL];

__device__ __forceinline__ unsigned f2tf(float x) {
    unsigned u;
    asm("cvt.rna.tf32.f32 %0, %1;" : "=r"(u) : "f"(x));
    return u;
}
__device__ __forceinline__ float roundtf(float x) { return __uint_as_float(f2tf(x)); }

__device__ __forceinline__ void mma_tf32(float* c, const unsigned* a, const unsigned* b) {
    asm volatile(
        "mma.sync.aligned.m16n8k8.row.col.f32.tf32.tf32.f32 "
        "{%0,%1,%2,%3}, {%4,%5,%6,%7}, {%8,%9}, {%0,%1,%2,%3};"
        : "+f"(c[0]), "+f"(c[1]), "+f"(c[2]), "+f"(c[3])
        : "r"(a[0]), "r"(a[1]), "r"(a[2]), "r"(a[3]), "r"(b[0]), "r"(b[1]));
}

// Load one smem row's fragment words for all 8 k-steps: 4x LDS.128.
struct Frag8 { unsigned a[8]; unsigned b[8]; };
__device__ __forceinline__ void load_frag8(const unsigned* base, int t, Frag8& f) {
    const uint4* p = (const uint4*)base;
    uint4 x0 = p[t * 2], x1 = p[t * 2 + 1];
    uint4 y0 = p[(t + 4) * 2], y1 = p[(t + 4) * 2 + 1];
    f.a[0] = x0.x; f.a[1] = x0.y; f.a[2] = x0.z; f.a[3] = x0.w;
    f.a[4] = x1.x; f.a[5] = x1.y; f.a[6] = x1.z; f.a[7] = x1.w;
    f.b[0] = y0.x; f.b[1] = y0.y; f.b[2] = y0.z; f.b[3] = y0.w;
    f.b[4] = y1.x; f.b[5] = y1.y; f.b[6] = y1.z; f.b[7] = y1.w;
}

// ---------------------------------------------------------------------------
// prep_a: query -> g_a (tf32-rounded, PERM within each 64-wide k block)
// ---------------------------------------------------------------------------
__global__ __launch_bounds__(256)
void prep_a(const float* __restrict__ query)
{
    int idx = blockIdx.x * 256 + threadIdx.x;      // over 8192*128 float4s
    int m = idx >> 7, c4 = idx & 127;
    int k = c4 * 4;
    float4 v = *(const float4*)(query + (size_t)m * DMODEL + k);
    float* dst = g_a + (size_t)m * DMODEL + (k & ~63);
    dst[PERM((k + 0) & 63)] = roundtf(v.x);
    dst[PERM((k + 1) & 63)] = roundtf(v.y);
    dst[PERM((k + 2) & 63)] = roundtf(v.z);
    dst[PERM((k + 3) & 63)] = roundtf(v.w);
}

// ---------------------------------------------------------------------------
// prep_w: W[k][n] -> g_wt[z][n][(k&~63)+PERM(k&63)] tf32-rounded (smem tile)
// grid (n0/64=8, k0/64=8, 4)
// ---------------------------------------------------------------------------
__global__ __launch_bounds__(256)
void prep_w(const float* __restrict__ W0, const float* __restrict__ W1,
            const float* __restrict__ W2, const float* __restrict__ W3)
{
    __shared__ float sm[64][68];
    const int z = blockIdx.z;
    const float* __restrict__ W = (z == 0) ? W0 : (z == 1) ? W1 : (z == 2) ? W2 : W3;
    const int n0 = blockIdx.x * 64;
    const int k0 = blockIdx.y * 64;
    const int tid = threadIdx.x;

#pragma unroll
    for (int i = 0; i < 4; i++) {
        int f4 = tid + i * 256;
        int kr = f4 >> 4, nq = f4 & 15;
        float4 v = *(const float4*)(W + (size_t)(k0 + kr) * DMODEL + n0 + nq * 4);
        sm[nq * 4 + 0][PERM(kr)] = roundtf(v.x);
        sm[nq * 4 + 1][PERM(kr)] = roundtf(v.y);
        sm[nq * 4 + 2][PERM(kr)] = roundtf(v.z);
        sm[nq * 4 + 3][PERM(kr)] = roundtf(v.w);
    }
    __syncthreads();
    float* dstz = g_wt + (size_t)z * DMODEL * DMODEL;
#pragma unroll
    for (int i = 0; i < 4; i++) {
        int f4 = tid + i * 256;
        int nr = f4 >> 4, q = f4 & 15;
        *(float4*)(dstz + (size_t)(n0 + nr) * DMODEL + k0 + q * 4) =
            *(const float4*)&sm[nr][q * 4];
    }
}

// ---------------------------------------------------------------------------
// Fast tf32 GEMM: C[8192,512] = A @ W, operands pre-rounded + pre-permuted.
// block 256 = 8 warps (4M x 2N), tile 128x64, K-block 64, cp.async dbl-buffer.
// OUT=false: A=g_a, B=g_wt[z], epilogue -> g_q/g_k/g_v layouts
// OUT=true : A=g_o, B=g_wt[3], epilogue -> external out
// dynamic smem: As[2][128][68] + Bs[2][64][68] = 104448 B
// ---------------------------------------------------------------------------
#define GA_WORDS (128 * 68)
#define GB_WORDS (64 * 68)

template <bool OUT>
__global__ __launch_bounds__(256)
void gemm_fast(float* __restrict__ Cext)
{
    extern __shared__ unsigned gsm[];
    unsigned* Asm = gsm;                    // [2][128][68]
    unsigned* Bsm = gsm + 2 * GA_WORDS;     // [2][64][68]

    const int z = OUT ? 3 : blockIdx.z;
    const float* __restrict__ A = OUT ? g_o : g_a;
    const float* __restrict__ B = g_wt + (size_t)z * DMODEL * DMODEL;

    const int tid  = threadIdx.x;
    const int warp = tid >> 5, lane = tid & 31;
    const int g = lane >> 2, t = lane & 3;
    const int wm = warp & 3, wn = warp >> 2;
    const int m0 = blockIdx.y * 128;
    const int c0 = blockIdx.x * 64;

    const unsigned as_base = (unsigned)__cvta_generic_to_shared(Asm);
    const unsigned bs_base = (unsigned)__cvta_generic_to_shared(Bsm);

    float acc[2][4][4];
#pragma unroll
    for (int i = 0; i < 2; i++)
#pragma unroll
        for (int j = 0; j < 4; j++)
#pragma unroll
            for (int k = 0; k < 4; k++) acc[i][j][k] = 0.f;

    // A tile: 128 rows x 16 chunks(16B) = 2048 -> 8/thread
    // B tile:  64 rows x 16 chunks      = 1024 -> 4/thread
#define G_ISSUE(k0, buf)                                                              \
    {                                                                                 \
        _Pragma("unroll")                                                             \
        for (int i = 0; i < 8; i++) {                                                 \
            int f4  = tid + i * 256;                                                  \
            int row = f4 >> 4, q = f4 & 15;                                           \
            const float* src = A + (size_t)(m0 + row) * DMODEL + (k0) + q * 4;        \
            unsigned dst = as_base + ((buf) * GA_WORDS + row * 68 + q * 4) * 4;       \
            asm volatile("cp.async.cg.shared.global [%0], [%1], 16;\n"                \
                         :: "r"(dst), "l"(src));                                      \
        }                                                                             \
        _Pragma("unroll")                                                             \
        for (int i = 0; i < 4; i++) {                                                 \
            int f4  = tid + i * 256;                                                  \
            int row = f4 >> 4, q = f4 & 15;                                           \
            const float* src = B + (size_t)(c0 + row) * DMODEL + (k0) + q * 4;        \
            unsigned dst = bs_base + ((buf) * GB_WORDS + row * 68 + q * 4) * 4;       \
            asm volatile("cp.async.cg.shared.global [%0], [%1], 16;\n"                \
                         :: "r"(dst), "l"(src));                                      \
        }                                                                             \
        asm volatile("cp.async.commit_group;\n");                                     \
    }

    G_ISSUE(0, 0);

    for (int c = 0; c < DMODEL / 64; c++) {
        const int buf = c & 1;
        if (c + 1 < DMODEL / 64) {
            __syncthreads();
            G_ISSUE((c + 1) * 64, buf ^ 1);
            asm volatile("cp.async.wait_group 1;\n");
        } else {
            asm volatile("cp.async.wait_group 0;\n");
        }
        __syncthreads();

        const unsigned* Asb = Asm + buf * GA_WORDS;
        const unsigned* Bsb = Bsm + buf * GB_WORDS;

        Frag8 fa[4];
        load_frag8(Asb + (wm * 32 + g) * 68,      t, fa[0]);
        load_frag8(Asb + (wm * 32 + 8 + g) * 68,  t, fa[1]);
        load_frag8(Asb + (wm * 32 + 16 + g) * 68, t, fa[2]);
        load_frag8(Asb + (wm * 32 + 24 + g) * 68, t, fa[3]);

#pragma unroll
        for (int nt = 0; nt < 4; nt++) {
            Frag8 fb;
            load_frag8(Bsb + (wn * 32 + nt * 8 + g) * 68, t, fb);
#pragma unroll
            for (int ks = 0; ks < 8; ks++) {
                unsigned bfr[2] = {fb.a[ks], fb.b[ks]};
                unsigned af0[4] = {fa[0].a[ks], fa[1].a[ks], fa[0].b[ks], fa[1].b[ks]};
                mma_tf32(acc[0][nt], af0, bfr);
                unsigned af1[4] = {fa[2].a[ks], fa[3].a[ks], fa[2].b[ks], fa[3].b[ks]};
                mma_tf32(acc[1][nt], af1, bfr);
            }
        }
    }
#undef G_ISSUE

    // epilogue
#pragma unroll
    for (int mt = 0; mt < 2; mt++) {
#pragma unroll
        for (int nt = 0; nt < 4; nt++) {
#pragma unroll
            for (int half = 0; half < 2; half++) {
                int m = m0 + wm * 32 + mt * 16 + g + half * 8;
                int c = c0 + wn * 32 + nt * 8 + 2 * t;
                float v0 = acc[mt][nt][half * 2 + 0];
                float v1 = acc[mt][nt][half * 2 + 1];
                if (OUT) {
                    *(float2*)&Cext[(size_t)m * DMODEL + c] = make_float2(v0, v1);
                } else {
                    int b = m >> 11, n = m & 2047;
                    int hh = c >> 6, d = c & 63;
                    size_t bh = (size_t)b * HEADS + hh;
                    if (z == 0) {
                        *(float2*)&g_q[(bh * SEQ + n) * DIM_HEAD + d] =
                            make_float2(roundtf(v0 * QK_SCALE), roundtf(v1 * QK_SCALE));
                    } else if (z == 1) {
                        float* dst = &g_k[(bh * SEQ + n) * DIM_HEAD];
                        dst[PERM(d)]     = roundtf(v0);
                        dst[PERM(d + 1)] = roundtf(v1);
                    } else {
                        int np = (n & ~63) + PERM(n & 63);
                        g_v[(bh * DIM_HEAD + d) * SEQ + np]     = roundtf(v0);
                        g_v[(bh * DIM_HEAD + d + 1) * SEQ + np] = roundtf(v1);
                    }
                }
            }
        }
    }
}

// ---------------------------------------------------------------------------
// Flash attention: cp.async double-buffered staging of pre-laid-out K/V.
// Block = 128 query rows (8 warps x 16), key chunks of 64.
// __launch_bounds__(256, 2): cap 128 regs -> 2 CTAs/SM (16 warps).
// dynamic smem: Ks[2][64][68] + Vt[2][64][68] = 69632 B (2 CTAs = 139 KB ok)
// ---------------------------------------------------------------------------
#define CHUNK_WORDS (64 * 68)

__global__ __launch_bounds__(256, 2)
void attn_tf32(const float* __restrict__ bias)
{
    extern __shared__ unsigned smem_u[];
    unsigned* Ksm = smem_u;
    unsigned* Vsm = smem_u + 2 * CHUNK_WORDS;

    const int tid  = threadIdx.x;
    const int warp = tid >> 5, lane = tid & 31;
    const int g = lane >> 2, t = lane & 3;
    const int bh = blockIdx.y;
    const int h  = bh & (HEADS - 1);
    const int b  = bh >> 3;
    const int qw = blockIdx.x * 128 + warp * 16;

    const float* __restrict__ Qg = g_q + (size_t)bh * SEQ * DIM_HEAD;
    const float* __restrict__ Kg = g_k + (size_t)bh * SEQ * DIM_HEAD;
    const float* __restrict__ Vg = g_v + (size_t)bh * DIM_HEAD * SEQ;
    const float* __restrict__ bp0 = bias + ((size_t)h * SEQ + qw + g) * SEQ;
    const float* __restrict__ bp1 = bias + ((size_t)h * SEQ + qw + g + 8) * SEQ;

    const unsigned ks_base = (unsigned)__cvta_generic_to_shared(Ksm);
    const unsigned vs_base = (unsigned)__cvta_generic_to_shared(Vsm);

    unsigned qa[8][4];
#pragma unroll
    for (int s = 0; s < 8; s++) {
        qa[s][0] = __float_as_uint(Qg[(size_t)(qw + g)     * DIM_HEAD + 8 * s + t]);
        qa[s][1] = __float_as_uint(Qg[(size_t)(qw + g + 8) * DIM_HEAD + 8 * s + t]);
        qa[s][2] = __float_as_uint(Qg[(size_t)(qw + g)     * DIM_HEAD + 8 * s + t + 4]);
        qa[s][3] = __float_as_uint(Qg[(size_t)(qw + g + 8) * DIM_HEAD + 8 * s + t + 4]);
    }

    float o[8][4];
#pragma unroll
    for (int i = 0; i < 8; i++)
#pragma unroll
        for (int j = 0; j < 4; j++) o[i][j] = 0.f;

    float m0r = -1e30f, m1r = -1e30f, l0 = 0.f, l1 = 0.f;

    const int crow = tid >> 4;
    const int cq   = tid & 15;

#define ISSUE_CHUNK(kt, buf)                                                          \
    {                                                                                 \
        _Pragma("unroll")                                                             \
        for (int i = 0; i < 4; i++) {                                                 \
            int row = crow + i * 16;                                                  \
            unsigned off = ((buf) * CHUNK_WORDS + row * 68 + cq * 4) * 4;             \
            const float* ksrc = Kg + (size_t)((kt) + row) * DIM_HEAD + cq * 4;        \
            asm volatile("cp.async.cg.shared.global [%0], [%1], 16;\n"                \
                         :: "r"(ks_base + off), "l"(ksrc));                           \
            const float* vsrc = Vg + (size_t)row * SEQ + (kt) + cq * 4;               \
            asm volatile("cp.async.cg.shared.global [%0], [%1], 16;\n"                \
                         :: "r"(vs_base + off), "l"(vsrc));                           \
        }                                                                             \
        asm volatile("cp.async.commit_group;\n");                                     \
    }

    ISSUE_CHUNK(0, 0);

    for (int c = 0; c < SEQ / 64; c++) {
        const int buf = c & 1;
        const int kt = c * 64;
        if (c + 1 < SEQ / 64) {
            __syncthreads();
            ISSUE_CHUNK(kt + 64, buf ^ 1);
            asm volatile("cp.async.wait_group 1;\n");
        } else {
            asm volatile("cp.async.wait_group 0;\n");
        }
        __syncthreads();

        const unsigned* Ks = Ksm + buf * CHUNK_WORDS;
        const unsigned* Vt = Vsm + buf * CHUNK_WORDS;

        float s[8][4];
#pragma unroll
        for (int i = 0; i < 8; i++)
#pragma unroll
            for (int j = 0; j < 4; j++) s[i][j] = 0.f;

#pragma unroll
        for (int ntp = 0; ntp < 4; ntp++) {
            Frag8 f0, f1;
            load_frag8(Ks + (ntp * 16 + g) * 68,     t, f0);
            load_frag8(Ks + (ntp * 16 + 8 + g) * 68, t, f1);
#pragma unroll
            for (int ks = 0; ks < 8; ks++) {
                unsigned bf0[2] = {f0.a[ks], f0.b[ks]};
                mma_tf32(s[2 * ntp], qa[ks], bf0);
                unsigned bf1[2] = {f1.a[ks], f1.b[ks]};
                mma_tf32(s[2 * ntp + 1], qa[ks], bf1);
            }
        }

        float mx0 = m0r, mx1 = m1r;
#pragma unroll
        for (int nt = 0; nt < 8; nt++) {
            float2 bb0 = *(const float2*)(bp0 + kt + nt * 8 + 2 * t);
            float2 bb1 = *(const float2*)(bp1 + kt + nt * 8 + 2 * t);
            s[nt][0] += bb0.x; s[nt][1] += bb0.y;
            s[nt][2] += bb1.x; s[nt][3] += bb1.y;
            mx0 = fmaxf(mx0, fmaxf(s[nt][0], s[nt][1]));
            mx1 = fmaxf(mx1, fmaxf(s[nt][2], s[nt][3]));
        }
        mx0 = fmaxf(mx0, __shfl_xor_sync(FULLMASK, mx0, 1));
        mx0 = fmaxf(mx0, __shfl_xor_sync(FULLMASK, mx0, 2));
        mx1 = fmaxf(mx1, __shfl_xor_sync(FULLMASK, mx1, 1));
        mx1 = fmaxf(mx1, __shfl_xor_sync(FULLMASK, mx1, 2));

        const float cr0 = __expf(m0r - mx0);
        const float cr1 = __expf(m1r - mx1);
        m0r = mx0; m1r = mx1;

        float ls0 = 0.f, ls1 = 0.f;
#pragma unroll
        for (int nt = 0; nt < 8; nt++) {
            s[nt][0] = __expf(s[nt][0] - mx0);
            s[nt][1] = __expf(s[nt][1] - mx0);
            s[nt][2] = __expf(s[nt][2] - mx1);
            s[nt][3] = __expf(s[nt][3] - mx1);
            ls0 += s[nt][0] + s[nt][1];
            ls1 += s[nt][2] + s[nt][3];
            o[nt][0] *= cr0; o[nt][1] *= cr0;
            o[nt][2] *= cr1; o[nt][3] *= cr1;
        }
        ls0 += __shfl_xor_sync(FULLMASK, ls0, 1);
        ls0 += __shfl_xor_sync(FULLMASK, ls0, 2);
        ls1 += __shfl_xor_sync(FULLMASK, ls1, 1);
        ls1 += __shfl_xor_sync(FULLMASK, ls1, 2);
        l0 = l0 * cr0 + ls0;
        l1 = l1 * cr1 + ls1;

        // relayout P in place: C-frag -> A-frag (tf32 bits stored back in s)
        const int l0q = (lane & ~3) | (t >> 1);
        const int l1q = (lane & ~3) | (2 + (t >> 1));
        const bool odd = t & 1;
#pragma unroll
        for (int j = 0; j < 8; j++) {
            float v00 = __shfl_sync(FULLMASK, s[j][0], l0q);
            float v01 = __shfl_sync(FULLMASK, s[j][1], l0q);
            float v02 = __shfl_sync(FULLMASK, s[j][2], l0q);
            float v03 = __shfl_sync(FULLMASK, s[j][3], l0q);
            float v10 = __shfl_sync(FULLMASK, s[j][0], l1q);
            float v11 = __shfl_sync(FULLMASK, s[j][1], l1q);
            float v12 = __shfl_sync(FULLMASK, s[j][2], l1q);
            float v13 = __shfl_sync(FULLMASK, s[j][3], l1q);
            s[j][0] = __uint_as_float(f2tf(odd ? v01 : v00));
            s[j][1] = __uint_as_float(f2tf(odd ? v03 : v02));
            s[j][2] = __uint_as_float(f2tf(odd ? v11 : v10));
            s[j][3] = __uint_as_float(f2tf(odd ? v13 : v12));
        }

#pragma unroll
        for (int ntp = 0; ntp < 4; ntp++) {
            Frag8 f0, f1;
            load_frag8(Vt + (ntp * 16 + g) * 68,     t, f0);
            load_frag8(Vt + (ntp * 16 + 8 + g) * 68, t, f1);
#pragma unroll
            for (int j = 0; j < 8; j++) {
                unsigned paj[4] = {__float_as_uint(s[j][0]), __float_as_uint(s[j][1]),
                                   __float_as_uint(s[j][2]), __float_as_uint(s[j][3])};
                unsigned bf0[2] = {f0.a[j], f0.b[j]};
                mma_tf32(o[2 * ntp], paj, bf0);
                unsigned bf1[2] = {f1.a[j], f1.b[j]};
                mma_tf32(o[2 * ntp + 1], paj, bf1);
            }
        }
    }

    // normalize + write g_o (tf32-rounded, PERM'd for gemm_fast<OUT> A-path)
    const float inv0 = 1.f / l0, inv1 = 1.f / l1;
    float* __restrict__ Og = g_o + ((size_t)b * SEQ + qw) * DMODEL + h * DIM_HEAD;
#pragma unroll
    for (int nt = 0; nt < 8; nt++) {
        int cc = nt * 8 + 2 * t;            // even
        int p = PERM(cc);                   // PERM(cc+1) == p + 8
        Og[(size_t)g * DMODEL + p]           = roundtf(o[nt][0] * inv0);
        Og[(size_t)g * DMODEL + p + 8]       = roundtf(o[nt][1] * inv0);
        Og[(size_t)(g + 8) * DMODEL + p]     = roundtf(o[nt][2] * inv1);
        Og[(size_t)(g + 8) * DMODEL + p + 8] = roundtf(o[nt][3] * inv1);
    }
}

// ---------------------------------------------------------------------------
extern "C" void kernel_launch(void* const* d_in, const int* in_sizes, int n_in,
                              void* d_out, int out_size)
{
    const float* query = (const float*)d_in[0];
    const float* bias  = (const float*)d_in[1];
    const float* Wq    = (const float*)d_in[2];
    const float* Wk    = (const float*)d_in[3];
    const float* Wv    = (const float*)d_in[4];
    const float* Wout  = (const float*)d_in[5];
    float* out = (float*)d_out;

    const int attn_smem = 4 * CHUNK_WORDS * 4;           // 69632 B
    const int gemm_smem = 2 * (GA_WORDS + GB_WORDS) * 4; // 104448 B
    cudaFuncSetAttribute(attn_tf32, cudaFuncAttributeMaxDynamicSharedMemorySize,
                         attn_smem);
    cudaFuncSetAttribute(gemm_fast<false>, cudaFuncAttributeMaxDynamicSharedMemorySize,
                         gemm_smem);
    cudaFuncSetAttribute(gemm_fast<true>, cudaFuncAttributeMaxDynamicSharedMemorySize,
                         gemm_smem);

    prep_a<<<M_ROWS * (DMODEL / 4) / 256, 256>>>(query);
    prep_w<<<dim3(8, 8, 4), 256>>>(Wq, Wk, Wv, Wout);

    dim3 qkv_grid(DMODEL / 64, M_ROWS / 128, 3);   // (8, 64, 3)
    gemm_fast<false><<<qkv_grid, 256, gemm_smem>>>(nullptr);

    dim3 attn_grid(SEQ / 128, BATCH * HEADS);      // (16, 32)
    attn_tf32<<<attn_grid, 256, attn_smem>>>(bias);

    dim3 out_grid(DMODEL / 64, M_ROWS / 128);      // (8, 64)
    gemm_fast<true><<<out_grid, 256, gemm_smem>>>(out);
}

// round 12
// speedup vs baseline: 5.2231x; 1.4139x over previous
#include <cuda_runtime.h>
#include <cuda_fp16.h>

#define HEADS 8
#define DIM_HEAD 64
#define BATCH 4
#define SEQ 2048
#define DMODEL 512
#define M_ROWS (BATCH * SEQ)           // 8192
#define QK_SCALE 0.125f                // 64^-0.5
#define FULLMASK 0xffffffffu
#define PERM(c) ((((c) & 7) << 3) | ((c) >> 3))   // 64-wide word perm (tf32 GEMM path)
#define P32(w)  ((((w) & 7) << 2) | ((w) >> 3))   // 32-wide half2-word perm (fp16 attn)

// Scratch (device-global; no allocation allowed)
// g_a:  [m][(k&~63)+PERM(k&63)] query, tf32-rounded (fp32)
// g_wt: [z][n][(k&~63)+PERM(k&63)] transposed weights, tf32-rounded (fp32)
// g_q:  half [b,h,n][P32 half2-word perm of d]  (pre-scaled by QK_SCALE)
// g_k:  half [b,h,n][P32 half2-word perm of d]
// g_v:  half [b,h,d][(key&~63) + P32((key&63)/2)*2 + (key&1)]  (transposed)
// g_o:  fp32 [b,n][(c&~63)+PERM(c&63)] attn out, tf32-rounded
__device__ float  g_a[M_ROWS * DMODEL];
__device__ float  g_wt[4 * DMODEL * DMODEL];
__device__ __half g_q[BATCH * HEADS * SEQ * DIM_HEAD];
__device__ __half g_k[BATCH * HEADS * SEQ * DIM_HEAD];
__device__ __half g_v[BATCH * HEADS * SEQ * DIM_HEAD];
__device__ float  g_o[BATCH * SEQ * DMODEL];

__device__ __forceinline__ unsigned f2tf(float x) {
    unsigned u;
    asm("cvt.rna.tf32.f32 %0, %1;" : "=r"(u) : "f"(x));
    return u;
}
__device__ __forceinline__ float roundtf(float x) { return __uint_as_float(f2tf(x)); }

__device__ __forceinline__ void mma_tf32(float* c, const unsigned* a, const unsigned* b) {
    asm volatile(
        "mma.sync.aligned.m16n8k8.row.col.f32.tf32.tf32.f32 "
        "{%0,%1,%2,%3}, {%4,%5,%6,%7}, {%8,%9}, {%0,%1,%2,%3};"
        : "+f"(c[0]), "+f"(c[1]), "+f"(c[2]), "+f"(c[3])
        : "r"(a[0]), "r"(a[1]), "r"(a[2]), "r"(a[3]), "r"(b[0]), "r"(b[1]));
}

__device__ __forceinline__ void mma_f16(float* c, const unsigned* a, unsigned b0, unsigned b1) {
    asm volatile(
        "mma.sync.aligned.m16n8k16.row.col.f32.f16.f16.f32 "
        "{%0,%1,%2,%3}, {%4,%5,%6,%7}, {%8,%9}, {%0,%1,%2,%3};"
        : "+f"(c[0]), "+f"(c[1]), "+f"(c[2]), "+f"(c[3])
        : "r"(a[0]), "r"(a[1]), "r"(a[2]), "r"(a[3]), "r"(b0), "r"(b1));
}

__device__ __forceinline__ unsigned packh2(float lo, float hi) {
    __half2 h = __floats2half2_rn(lo, hi);
    return *(unsigned*)&h;
}

// tf32 GEMM fragment helper (unchanged)
struct Frag8 { unsigned a[8]; unsigned b[8]; };
__device__ __forceinline__ void load_frag8(const unsigned* base, int t, Frag8& f) {
    const uint4* p = (const uint4*)base;
    uint4 x0 = p[t * 2], x1 = p[t * 2 + 1];
    uint4 y0 = p[(t + 4) * 2], y1 = p[(t + 4) * 2 + 1];
    f.a[0] = x0.x; f.a[1] = x0.y; f.a[2] = x0.z; f.a[3] = x0.w;
    f.a[4] = x1.x; f.a[5] = x1.y; f.a[6] = x1.z; f.a[7] = x1.w;
    f.b[0] = y0.x; f.b[1] = y0.y; f.b[2] = y0.z; f.b[3] = y0.w;
    f.b[4] = y1.x; f.b[5] = y1.y; f.b[6] = y1.z; f.b[7] = y1.w;
}

// ---------------------------------------------------------------------------
// prep_a / prep_w : unchanged tf32 paths
// ---------------------------------------------------------------------------
__global__ __launch_bounds__(256)
void prep_a(const float* __restrict__ query)
{
    int idx = blockIdx.x * 256 + threadIdx.x;
    int m = idx >> 7, c4 = idx & 127;
    int k = c4 * 4;
    float4 v = *(const float4*)(query + (size_t)m * DMODEL + k);
    float* dst = g_a + (size_t)m * DMODEL + (k & ~63);
    dst[PERM((k + 0) & 63)] = roundtf(v.x);
    dst[PERM((k + 1) & 63)] = roundtf(v.y);
    dst[PERM((k + 2) & 63)] = roundtf(v.z);
    dst[PERM((k + 3) & 63)] = roundtf(v.w);
}

__global__ __launch_bounds__(256)
void prep_w(const float* __restrict__ W0, const float* __restrict__ W1,
            const float* __restrict__ W2, const float* __restrict__ W3)
{
    __shared__ float sm[64][68];
    const int z = blockIdx.z;
    const float* __restrict__ W = (z == 0) ? W0 : (z == 1) ? W1 : (z == 2) ? W2 : W3;
    const int n0 = blockIdx.x * 64;
    const int k0 = blockIdx.y * 64;
    const int tid = threadIdx.x;

#pragma unroll
    for (int i = 0; i < 4; i++) {
        int f4 = tid + i * 256;
        int kr = f4 >> 4, nq = f4 & 15;
        float4 v = *(const float4*)(W + (size_t)(k0 + kr) * DMODEL + n0 + nq * 4);
        sm[nq * 4 + 0][PERM(kr)] = roundtf(v.x);
        sm[nq * 4 + 1][PERM(kr)] = roundtf(v.y);
        sm[nq * 4 + 2][PERM(kr)] = roundtf(v.z);
        sm[nq * 4 + 3][PERM(kr)] = roundtf(v.w);
    }
    __syncthreads();
    float* dstz = g_wt + (size_t)z * DMODEL * DMODEL;
#pragma unroll
    for (int i = 0; i < 4; i++) {
        int f4 = tid + i * 256;
        int nr = f4 >> 4, q = f4 & 15;
        *(float4*)(dstz + (size_t)(n0 + nr) * DMODEL + k0 + q * 4) =
            *(const float4*)&sm[nr][q * 4];
    }
}

// ---------------------------------------------------------------------------
// tf32 GEMM (unchanged mainloop); epilogue now writes fp16 attn layouts.
// ---------------------------------------------------------------------------
#define GA_WORDS (128 * 68)
#define GB_WORDS (64 * 68)

template <bool OUT>
__global__ __launch_bounds__(256)
void gemm_fast(float* __restrict__ Cext)
{
    extern __shared__ unsigned gsm[];
    unsigned* Asm = gsm;
    unsigned* Bsm = gsm + 2 * GA_WORDS;

    const int z = OUT ? 3 : blockIdx.z;
    const float* __restrict__ A = OUT ? g_o : g_a;
    const float* __restrict__ B = g_wt + (size_t)z * DMODEL * DMODEL;

    const int tid  = threadIdx.x;
    const int warp = tid >> 5, lane = tid & 31;
    const int g = lane >> 2, t = lane & 3;
    const int wm = warp & 3, wn = warp >> 2;
    const int m0 = blockIdx.y * 128;
    const int c0 = blockIdx.x * 64;

    const unsigned as_base = (unsigned)__cvta_generic_to_shared(Asm);
    const unsigned bs_base = (unsigned)__cvta_generic_to_shared(Bsm);

    float acc[2][4][4];
#pragma unroll
    for (int i = 0; i < 2; i++)
#pragma unroll
        for (int j = 0; j < 4; j++)
#pragma unroll
            for (int k = 0; k < 4; k++) acc[i][j][k] = 0.f;

#define G_ISSUE(k0, buf)                                                              \
    {                                                                                 \
        _Pragma("unroll")                                                             \
        for (int i = 0; i < 8; i++) {                                                 \
            int f4  = tid + i * 256;                                                  \
            int row = f4 >> 4, q = f4 & 15;                                           \
            const float* src = A + (size_t)(m0 + row) * DMODEL + (k0) + q * 4;        \
            unsigned dst = as_base + ((buf) * GA_WORDS + row * 68 + q * 4) * 4;       \
            asm volatile("cp.async.cg.shared.global [%0], [%1], 16;\n"                \
                         :: "r"(dst), "l"(src));                                      \
        }                                                                             \
        _Pragma("unroll")                                                             \
        for (int i = 0; i < 4; i++) {                                                 \
            int f4  = tid + i * 256;                                                  \
            int row = f4 >> 4, q = f4 & 15;                                           \
            const float* src = B + (size_t)(c0 + row) * DMODEL + (k0) + q * 4;        \
            unsigned dst = bs_base + ((buf) * GB_WORDS + row * 68 + q * 4) * 4;       \
            asm volatile("cp.async.cg.shared.global [%0], [%1], 16;\n"                \
                         :: "r"(dst), "l"(src));                                      \
        }                                                                             \
        asm volatile("cp.async.commit_group;\n");                                     \
    }

    G_ISSUE(0, 0);

    for (int c = 0; c < DMODEL / 64; c++) {
        const int buf = c & 1;
        if (c + 1 < DMODEL / 64) {
            __syncthreads();
            G_ISSUE((c + 1) * 64, buf ^ 1);
            asm volatile("cp.async.wait_group 1;\n");
        } else {
            asm volatile("cp.async.wait_group 0;\n");
        }
        __syncthreads();

        const unsigned* Asb = Asm + buf * GA_WORDS;
        const unsigned* Bsb = Bsm + buf * GB_WORDS;

        Frag8 fa[4];
        load_frag8(Asb + (wm * 32 + g) * 68,      t, fa[0]);
        load_frag8(Asb + (wm * 32 + 8 + g) * 68,  t, fa[1]);
        load_frag8(Asb + (wm * 32 + 16 + g) * 68, t, fa[2]);
        load_frag8(Asb + (wm * 32 + 24 + g) * 68, t, fa[3]);

#pragma unroll
        for (int nt = 0; nt < 4; nt++) {
            Frag8 fb;
            load_frag8(Bsb + (wn * 32 + nt * 8 + g) * 68, t, fb);
#pragma unroll
            for (int ks = 0; ks < 8; ks++) {
                unsigned bfr[2] = {fb.a[ks], fb.b[ks]};
                unsigned af0[4] = {fa[0].a[ks], fa[1].a[ks], fa[0].b[ks], fa[1].b[ks]};
                mma_tf32(acc[0][nt], af0, bfr);
                unsigned af1[4] = {fa[2].a[ks], fa[3].a[ks], fa[2].b[ks], fa[3].b[ks]};
                mma_tf32(acc[1][nt], af1, bfr);
            }
        }
    }
#undef G_ISSUE

#pragma unroll
    for (int mt = 0; mt < 2; mt++) {
#pragma unroll
        for (int nt = 0; nt < 4; nt++) {
#pragma unroll
            for (int half = 0; half < 2; half++) {
                int m = m0 + wm * 32 + mt * 16 + g + half * 8;
                int c = c0 + wn * 32 + nt * 8 + 2 * t;
                float v0 = acc[mt][nt][half * 2 + 0];
                float v1 = acc[mt][nt][half * 2 + 1];
                if (OUT) {
                    *(float2*)&Cext[(size_t)m * DMODEL + c] = make_float2(v0, v1);
                } else {
                    int b = m >> 11, n = m & 2047;
                    int hh = c >> 6, d = c & 63;   // d even
                    size_t bh = (size_t)b * HEADS + hh;
                    if (z == 0) {
                        int p = P32(d >> 1);
                        ((__half2*)(g_q + (bh * SEQ + n) * DIM_HEAD))[p] =
                            __floats2half2_rn(v0 * QK_SCALE, v1 * QK_SCALE);
                    } else if (z == 1) {
                        int p = P32(d >> 1);
                        ((__half2*)(g_k + (bh * SEQ + n) * DIM_HEAD))[p] =
                            __floats2half2_rn(v0, v1);
                    } else {
                        int w = (n & 63) >> 1;
                        size_t col = (size_t)(n & ~63) + P32(w) * 2 + (n & 1);
                        g_v[(bh * DIM_HEAD + d) * SEQ + col]     = __float2half(v0);
                        g_v[(bh * DIM_HEAD + d + 1) * SEQ + col] = __float2half(v1);
                    }
                }
            }
        }
    }
}

// ---------------------------------------------------------------------------
// Flash attention, fp16 m16n8k16. Block = 128 query rows (8 warps x 16),
// key chunks of 64. K/V half tiles staged via cp.async, double-buffered.
// Smem row stride 48 words (192B) -> conflict-free LDS.128 fragment loads.
// No P-relayout shuffles: m16n8k16 A-frag == two stacked m16n8k8 C-frags.
// dynamic smem: 4 tiles x 64 x 48 words = 49152 B
// ---------------------------------------------------------------------------
#define KROW_W 48
#define TILE_WORDS (64 * KROW_W)

__global__ __launch_bounds__(256, 2)
void attn_f16(const float* __restrict__ bias)
{
    extern __shared__ unsigned smem_u[];
    unsigned* Ksm = smem_u;                    // [2][64][48]
    unsigned* Vsm = smem_u + 2 * TILE_WORDS;   // [2][64][48]

    const int tid  = threadIdx.x;
    const int warp = tid >> 5, lane = tid & 31;
    const int g = lane >> 2, t = lane & 3;
    const int bh = blockIdx.y;
    const int h  = bh & (HEADS - 1);
    const int b  = bh >> 3;
    const int qw = blockIdx.x * 128 + warp * 16;

    const __half* __restrict__ Qg = g_q + (size_t)bh * SEQ * DIM_HEAD;
    const __half* __restrict__ Kg = g_k + (size_t)bh * SEQ * DIM_HEAD;
    const __half* __restrict__ Vg = g_v + (size_t)bh * DIM_HEAD * SEQ;
    const float*  __restrict__ bp0 = bias + ((size_t)h * SEQ + qw + g) * SEQ;
    const float*  __restrict__ bp1 = bias + ((size_t)h * SEQ + qw + g + 8) * SEQ;

    const unsigned ks_base = (unsigned)__cvta_generic_to_shared(Ksm);
    const unsigned vs_base = (unsigned)__cvta_generic_to_shared(Vsm);

    // Q A-frags: per kstep {rowg@w, rowg8@w, rowg@w+4, rowg8@w+4}, w = ks*8+t
    unsigned qa[4][4];
    {
        const uint4* Qr0 = (const uint4*)(Qg + (size_t)(qw + g) * DIM_HEAD);
        const uint4* Qr1 = (const uint4*)(Qg + (size_t)(qw + g + 8) * DIM_HEAD);
        uint4 qx0 = Qr0[t], qy0 = Qr0[t + 4];
        uint4 qx1 = Qr1[t], qy1 = Qr1[t + 4];
        const unsigned* px0 = (const unsigned*)&qx0;
        const unsigned* py0 = (const unsigned*)&qy0;
        const unsigned* px1 = (const unsigned*)&qx1;
        const unsigned* py1 = (const unsigned*)&qy1;
#pragma unroll
        for (int ks = 0; ks < 4; ks++) {
            qa[ks][0] = px0[ks]; qa[ks][1] = px1[ks];
            qa[ks][2] = py0[ks]; qa[ks][3] = py1[ks];
        }
    }

    float o[8][4];
#pragma unroll
    for (int i = 0; i < 8; i++)
#pragma unroll
        for (int j = 0; j < 4; j++) o[i][j] = 0.f;

    float m0r = -1e30f, m1r = -1e30f, l0 = 0.f, l1 = 0.f;

    // staging: K tile 64 rows x 8 chunks(16B) = 512; V same; 4 chunks/thread
#define ISSUE_CHUNK(kt, buf)                                                          \
    {                                                                                 \
        _Pragma("unroll")                                                             \
        for (int i = 0; i < 2; i++) {                                                 \
            int cidx = tid + i * 256;                                                 \
            int row = cidx >> 3, q = cidx & 7;                                        \
            unsigned off = ((buf) * TILE_WORDS + row * KROW_W + q * 4) * 4;           \
            const __half* ksrc = Kg + (size_t)((kt) + row) * DIM_HEAD + q * 8;        \
            asm volatile("cp.async.cg.shared.global [%0], [%1], 16;\n"                \
                         :: "r"(ks_base + off), "l"(ksrc));                           \
            const __half* vsrc = Vg + (size_t)row * SEQ + (kt) + q * 8;               \
            asm volatile("cp.async.cg.shared.global [%0], [%1], 16;\n"                \
                         :: "r"(vs_base + off), "l"(vsrc));                           \
        }                                                                             \
        asm volatile("cp.async.commit_group;\n");                                     \
    }

    ISSUE_CHUNK(0, 0);

    for (int c = 0; c < SEQ / 64; c++) {
        const int buf = c & 1;
        const int kt = c * 64;
        if (c + 1 < SEQ / 64) {
            __syncthreads();
            ISSUE_CHUNK(kt + 64, buf ^ 1);
            asm volatile("cp.async.wait_group 1;\n");
        } else {
            asm volatile("cp.async.wait_group 0;\n");
        }
        __syncthreads();

        const unsigned* Ks = Ksm + buf * TILE_WORDS;
        const unsigned* Vt = Vsm + buf * TILE_WORDS;

        // S = Q K^T : 8 key-groups of 8, 4 k-steps of 16
        float s[8][4];
#pragma unroll
        for (int i = 0; i < 8; i++)
#pragma unroll
            for (int j = 0; j < 4; j++) s[i][j] = 0.f;

#pragma unroll
        for (int p = 0; p < 4; p++) {
            const unsigned* r0 = Ks + ((2 * p) * 8 + g) * KROW_W;
            const unsigned* r1 = Ks + ((2 * p + 1) * 8 + g) * KROW_W;
            uint4 x0 = *(const uint4*)(r0 + t * 4), y0 = *(const uint4*)(r0 + (t + 4) * 4);
            uint4 x1 = *(const uint4*)(r1 + t * 4), y1 = *(const uint4*)(r1 + (t + 4) * 4);
            const unsigned* ax0 = (const unsigned*)&x0;
            const unsigned* ay0 = (const unsigned*)&y0;
            const unsigned* ax1 = (const unsigned*)&x1;
            const unsigned* ay1 = (const unsigned*)&y1;
#pragma unroll
            for (int ks = 0; ks < 4; ks++) {
                mma_f16(s[2 * p],     qa[ks], ax0[ks], ay0[ks]);
                mma_f16(s[2 * p + 1], qa[ks], ax1[ks], ay1[ks]);
            }
        }

        // bias + running max
        float mx0 = m0r, mx1 = m1r;
#pragma unroll
        for (int nt = 0; nt < 8; nt++) {
            float2 bb0 = *(const float2*)(bp0 + kt + nt * 8 + 2 * t);
            float2 bb1 = *(const float2*)(bp1 + kt + nt * 8 + 2 * t);
            s[nt][0] += bb0.x; s[nt][1] += bb0.y;
            s[nt][2] += bb1.x; s[nt][3] += bb1.y;
            mx0 = fmaxf(mx0, fmaxf(s[nt][0], s[nt][1]));
            mx1 = fmaxf(mx1, fmaxf(s[nt][2], s[nt][3]));
        }
        mx0 = fmaxf(mx0, __shfl_xor_sync(FULLMASK, mx0, 1));
        mx0 = fmaxf(mx0, __shfl_xor_sync(FULLMASK, mx0, 2));
        mx1 = fmaxf(mx1, __shfl_xor_sync(FULLMASK, mx1, 1));
        mx1 = fmaxf(mx1, __shfl_xor_sync(FULLMASK, mx1, 2));

        const float cr0 = __expf(m0r - mx0);
        const float cr1 = __expf(m1r - mx1);
        m0r = mx0; m1r = mx1;

        float ls0 = 0.f, ls1 = 0.f;
#pragma unroll
        for (int nt = 0; nt < 8; nt++) {
            s[nt][0] = __expf(s[nt][0] - mx0);
            s[nt][1] = __expf(s[nt][1] - mx0);
            s[nt][2] = __expf(s[nt][2] - mx1);
            s[nt][3] = __expf(s[nt][3] - mx1);
            ls0 += s[nt][0] + s[nt][1];
            ls1 += s[nt][2] + s[nt][3];
            o[nt][0] *= cr0; o[nt][1] *= cr0;
            o[nt][2] *= cr1; o[nt][3] *= cr1;
        }
        ls0 += __shfl_xor_sync(FULLMASK, ls0, 1);
        ls0 += __shfl_xor_sync(FULLMASK, ls0, 2);
        ls1 += __shfl_xor_sync(FULLMASK, ls1, 1);
        ls1 += __shfl_xor_sync(FULLMASK, ls1, 2);
        l0 = l0 * cr0 + ls0;
        l1 = l1 * cr1 + ls1;

        // P -> fp16 A-frags: NO shuffles (A-frag == two stacked C-frags)
        unsigned pa[4][4];
#pragma unroll
        for (int j = 0; j < 4; j++) {
            pa[j][0] = packh2(s[2 * j][0],     s[2 * j][1]);
            pa[j][1] = packh2(s[2 * j][2],     s[2 * j][3]);
            pa[j][2] = packh2(s[2 * j + 1][0], s[2 * j + 1][1]);
            pa[j][3] = packh2(s[2 * j + 1][2], s[2 * j + 1][3]);
        }

        // O += P @ V : 8 dh-groups of 8, 4 key-steps of 16
#pragma unroll
        for (int p = 0; p < 4; p++) {
            const unsigned* r0 = Vt + ((2 * p) * 8 + g) * KROW_W;
            const unsigned* r1 = Vt + ((2 * p + 1) * 8 + g) * KROW_W;
            uint4 x0 = *(const uint4*)(r0 + t * 4), y0 = *(const uint4*)(r0 + (t + 4) * 4);
            uint4 x1 = *(const uint4*)(r1 + t * 4), y1 = *(const uint4*)(r1 + (t + 4) * 4);
            const unsigned* ax0 = (const unsigned*)&x0;
            const unsigned* ay0 = (const unsigned*)&y0;
            const unsigned* ax1 = (const unsigned*)&x1;
            const unsigned* ay1 = (const unsigned*)&y1;
#pragma unroll
            for (int j = 0; j < 4; j++) {
                mma_f16(o[2 * p],     pa[j], ax0[j], ay0[j]);
                mma_f16(o[2 * p + 1], pa[j], ax1[j], ay1[j]);
            }
        }
    }

    // normalize + write g_o (tf32-rounded, PERM'd for gemm_fast<OUT> A-path)
    const float inv0 = 1.f / l0, inv1 = 1.f / l1;
    float* __restrict__ Og = g_o + ((size_t)b * SEQ + qw) * DMODEL + h * DIM_HEAD;
#pragma unroll
    for (int nt = 0; nt < 8; nt++) {
        int cc = nt * 8 + 2 * t;            // even
        int p = PERM(cc);                   // PERM(cc+1) == p + 8
        Og[(size_t)g * DMODEL + p]           = roundtf(o[nt][0] * inv0);
        Og[(size_t)g * DMODEL + p + 8]       = roundtf(o[nt][1] * inv0);
        Og[(size_t)(g + 8) * DMODEL + p]     = roundtf(o[nt][2] * inv1);
        Og[(size_t)(g + 8) * DMODEL + p + 8] = roundtf(o[nt][3] * inv1);
    }
}

// ---------------------------------------------------------------------------
extern "C" void kernel_launch(void* const* d_in, const int* in_sizes, int n_in,
                              void* d_out, int out_size)
{
    const float* query = (const float*)d_in[0];
    const float* bias  = (const float*)d_in[1];
    const float* Wq    = (const float*)d_in[2];
    const float* Wk    = (const float*)d_in[3];
    const float* Wv    = (const float*)d_in[4];
    const float* Wout  = (const float*)d_in[5];
    float* out = (float*)d_out;

    const int attn_smem = 4 * TILE_WORDS * 4;            // 49152 B
    const int gemm_smem = 2 * (GA_WORDS + GB_WORDS) * 4; // 104448 B
    cudaFuncSetAttribute(attn_f16, cudaFuncAttributeMaxDynamicSharedMemorySize,
                         attn_smem);
    cudaFuncSetAttribute(gemm_fast<false>, cudaFuncAttributeMaxDynamicSharedMemorySize,
                         gemm_smem);
    cudaFuncSetAttribute(gemm_fast<true>, cudaFuncAttributeMaxDynamicSharedMemorySize,
                         gemm_smem);

    prep_a<<<M_ROWS * (DMODEL / 4) / 256, 256>>>(query);
    prep_w<<<dim3(8, 8, 4), 256>>>(Wq, Wk, Wv, Wout);

    dim3 qkv_grid(DMODEL / 64, M_ROWS / 128, 3);   // (8, 64, 3)
    gemm_fast<false><<<qkv_grid, 256, gemm_smem>>>(nullptr);

    dim3 attn_grid(SEQ / 128, BATCH * HEADS);      // (16, 32)
    attn_f16<<<attn_grid, 256, attn_smem>>>(bias);

    dim3 out_grid(DMODEL / 64, M_ROWS / 128);      // (8, 64)
    gemm_fast<true><<<out_grid, 256, gemm_smem>>>(out);
}